// round 2
// baseline (speedup 1.0000x reference)
#include <cuda_runtime.h>
#include <math.h>

// Problem constants
#define VD 16384
#define ED 1024
#define HD 1024
#define H2 2048
#define LD 2
#define BD 128
#define TD 256
#define SD 64
#define TB 32768   // B*T

// ---------------- scratch (__device__ globals; no allocations allowed) -------------
__device__ float g_X [(size_t)TB * HD];   // projected inputs, [T,B,H]
__device__ float g_XG[(size_t)TB * H2];   // per-layer x-gate proj, [T,B,2H]
__device__ float g_XC[(size_t)TB * HD];   // per-layer x-cand proj, [T,B,H]
__device__ float g_O0[(size_t)TB * HD];   // layer0 output seq, [T,B,H]
__device__ float g_O1[(size_t)TB * HD];   // layer1 output seq, [T,B,H]
__device__ float g_h [BD * HD];           // recurrent state
__device__ float g_RH[BD * HD];           // r*h
__device__ float g_U [BD * HD];           // update gate
__device__ float g_sampWT[HD * SD];       // gathered sampled softmax rows, transposed [H,S]
__device__ float g_sampB [SD];
__device__ int   g_rowidx[TB];            // token id for row (t*B+b)
__device__ unsigned g_barcnt;             // software grid barrier counter

__device__ __forceinline__ float softplusf(float x) {
    return fmaxf(x, 0.f) + log1pf(expf(-fabsf(x)));
}

// software grid barrier: all CTAs of the persistent kernel are co-resident
__device__ __forceinline__ void gsync(unsigned target) {
    __syncthreads();
    if (threadIdx.x == 0) {
        __threadfence();
        atomicAdd(&g_barcnt, 1u);
        while (*(volatile unsigned*)&g_barcnt < target) __nanosleep(32);
        __threadfence();
    }
    __syncthreads();
}

// ---------------- tiny helper kernels ----------------
__global__ void k_zero_out(float* p, int n) {
    int i = blockIdx.x * blockDim.x + threadIdx.x;
    if (i < n) p[i] = 0.f;
}

__global__ void k_zero_bar() { g_barcnt = 0u; }

__global__ void k_rowidx(const int* __restrict__ input_data) {
    int r = blockIdx.x * blockDim.x + threadIdx.x;
    if (r < TB) {
        int t = r >> 7;         // r / B
        int b = r & 127;        // r % B
        g_rowidx[r] = input_data[b * TD + t];
    }
}

__global__ void k_gather_samp(const int* __restrict__ nce,
                              const float* __restrict__ sw,
                              const float* __restrict__ sb) {
    int s = blockIdx.x;
    int row = nce[s];
    const float* src = sw + (size_t)row * HD;
    for (int k = threadIdx.x; k < HD; k += blockDim.x)
        g_sampWT[k * SD + s] = src[k];
    if (threadIdx.x == 0) g_sampB[s] = sb[row];
}

// ---------------- generic 128x128x8 SGEMM (optional A-row gather, optional bias) ----
template<bool GATHER, bool BIAS>
__global__ __launch_bounds__(256)
void k_sgemm(const float* __restrict__ A, const float* __restrict__ Bm,
             const float* __restrict__ bias, float* __restrict__ C,
             int M, int N, int K, const int* __restrict__ gidx)
{
    __shared__ float As[8][132];
    __shared__ float Bs[8][128];
    const int tid = threadIdx.x;
    const int rowBase = blockIdx.y * 128;
    const int colBase = blockIdx.x * 128;

    const int arow = tid >> 1;
    const int acol = (tid & 1) << 2;
    size_t aoff;
    if (GATHER) aoff = (size_t)gidx[rowBase + arow] * K;
    else        aoff = (size_t)(rowBase + arow) * K;

    const int brow = tid >> 5;
    const int bcol = (tid & 31) << 2;

    const int ty = tid >> 4;   // 0..15
    const int tx = tid & 15;   // 0..15

    float acc[8][8];
    #pragma unroll
    for (int i = 0; i < 8; i++)
        #pragma unroll
        for (int j = 0; j < 8; j++) acc[i][j] = 0.f;

    for (int k0 = 0; k0 < K; k0 += 8) {
        float4 av = *(const float4*)(A + aoff + k0 + acol);
        As[acol + 0][arow] = av.x;
        As[acol + 1][arow] = av.y;
        As[acol + 2][arow] = av.z;
        As[acol + 3][arow] = av.w;
        *(float4*)&Bs[brow][bcol] =
            *(const float4*)(Bm + (size_t)(k0 + brow) * N + colBase + bcol);
        __syncthreads();
        #pragma unroll
        for (int k = 0; k < 8; k++) {
            float ar[8], br[8];
            *(float4*)&ar[0] = *(const float4*)&As[k][ty * 8];
            *(float4*)&ar[4] = *(const float4*)&As[k][ty * 8 + 4];
            *(float4*)&br[0] = *(const float4*)&Bs[k][tx * 8];
            *(float4*)&br[4] = *(const float4*)&Bs[k][tx * 8 + 4];
            #pragma unroll
            for (int i = 0; i < 8; i++)
                #pragma unroll
                for (int j = 0; j < 8; j++)
                    acc[i][j] += ar[i] * br[j];
        }
        __syncthreads();
    }

    #pragma unroll
    for (int i = 0; i < 8; i++) {
        size_t row = (size_t)(rowBase + ty * 8 + i);
        float* crow = C + row * N + colBase + tx * 8;
        #pragma unroll
        for (int j = 0; j < 8; j += 4) {
            float4 v;
            v.x = acc[i][j + 0]; v.y = acc[i][j + 1];
            v.z = acc[i][j + 2]; v.w = acc[i][j + 3];
            if (BIAS) {
                const float* bp = bias + colBase + tx * 8 + j;
                v.x += bp[0]; v.y += bp[1]; v.z += bp[2]; v.w += bp[3];
            }
            *(float4*)(crow + j) = v;
        }
    }
}

// ---------------- persistent per-layer MI-GRU recurrence --------------------------
// 128 CTAs x 256 threads, all co-resident. Each CTA owns gate cols [cta*16,+16)
// and cand cols [cta*8,+8). Two grid barriers per timestep.
// Inter-CTA arrays (g_h, g_RH, g_U) use .cg loads/stores (L1 is not coherent).
__global__ __launch_bounds__(256)
void k_layer(const float* __restrict__ Whg, const float* __restrict__ Whc,
             const float* __restrict__ XG, const float* __restrict__ XC,
             const float* __restrict__ ag, const float* __restrict__ b1g,
             const float* __restrict__ b2g, const float* __restrict__ bg,
             const float* __restrict__ ac, const float* __restrict__ b1c,
             const float* __restrict__ b2c, const float* __restrict__ bcv,
             float* __restrict__ outseq, unsigned barBase)
{
    __shared__ float As[32][132];
    __shared__ float Bs[32][16];

    const int cta = blockIdx.x;          // 0..127
    const unsigned nCTA = gridDim.x;     // 128
    const int tid = threadIdx.x;

    // shared A-staging mapping (both phases)
    const int arow  = tid >> 1;          // 0..127
    const int khalf = (tid & 1) << 2;    // 0 or 4

    // gate phase mapping: tile 128 rows x 16 cols
    const int gcol0 = cta * 16;
    const int gtx = tid & 15;
    const int gty = tid >> 4;            // rows gty*8..gty*8+7
    const int bkk = tid >> 3;            // 0..31 (B k index)
    const int gbc = (tid & 7) << 1;      // B col pair
    const int gj  = gcol0 + gtx;
    const float agj = ag[gj], b1gj = b1g[gj], b2gj = b2g[gj], bgj = bg[gj];

    // cand phase mapping: tile 128 rows x 8 cols
    const int ccol0 = cta * 8;
    const int ctx = tid & 7;
    const int cty = tid >> 3;            // rows cty*4..cty*4+3
    const int cbc = tid & 7;
    const int cj  = ccol0 + ctx;
    const float acj = ac[cj], b1cj = b1c[cj], b2cj = b2c[cj], bcj = bcv[cj];

    // zero initial hidden state (BD*HD floats: 1024 per CTA, 4 per thread)
    {
        float4 z = make_float4(0.f, 0.f, 0.f, 0.f);
        __stcg((float4*)(g_h + cta * 1024 + tid * 4), z);
    }
    unsigned bar = barBase + 1;
    gsync(bar * nCTA);

    for (int t = 0; t < TD; t++) {
        // ---- gate phase: gh = h @ Whg[:, gcol0:gcol0+16], then sigmoid gate ----
        {
            const float* gx = XG + (size_t)t * BD * H2;
            float acc[8] = {0.f,0.f,0.f,0.f,0.f,0.f,0.f,0.f};
            for (int k0 = 0; k0 < HD; k0 += 32) {
                #pragma unroll
                for (int q = 0; q < 4; q++) {
                    int kk = q * 8 + khalf;
                    float4 v = __ldcg((const float4*)(g_h + arow * HD + k0 + kk));
                    As[kk + 0][arow] = v.x;
                    As[kk + 1][arow] = v.y;
                    As[kk + 2][arow] = v.z;
                    As[kk + 3][arow] = v.w;
                }
                float2 w = *(const float2*)(Whg + (size_t)(k0 + bkk) * H2 + gcol0 + gbc);
                Bs[bkk][gbc]     = w.x;
                Bs[bkk][gbc + 1] = w.y;
                __syncthreads();
                #pragma unroll
                for (int k = 0; k < 32; k++) {
                    float bv = Bs[k][gtx];
                    float4 a0 = *(const float4*)&As[k][gty * 8];
                    float4 a1 = *(const float4*)&As[k][gty * 8 + 4];
                    acc[0] += a0.x * bv; acc[1] += a0.y * bv;
                    acc[2] += a0.z * bv; acc[3] += a0.w * bv;
                    acc[4] += a1.x * bv; acc[5] += a1.y * bv;
                    acc[6] += a1.z * bv; acc[7] += a1.w * bv;
                }
                __syncthreads();
            }
            #pragma unroll
            for (int i = 0; i < 8; i++) {
                int row = gty * 8 + i;
                float gxv = gx[row * H2 + gj];
                float ghv = acc[i];
                float z = agj * gxv * ghv + b1gj * gxv + b2gj * ghv + bgj;
                float g = 1.f / (1.f + expf(-z));
                if (gj < HD) {
                    float hv = __ldcg(g_h + row * HD + gj);
                    __stcg(g_RH + row * HD + gj, g * hv);
                } else {
                    __stcg(g_U + row * HD + (gj - HD), g);
                }
            }
        }
        bar++; gsync(bar * nCTA);

        // ---- cand phase: ch = (r*h) @ Whc[:, ccol0:ccol0+8], tanh, state update ----
        {
            const float* cx = XC + (size_t)t * BD * HD;
            float acc[4] = {0.f, 0.f, 0.f, 0.f};
            for (int k0 = 0; k0 < HD; k0 += 32) {
                #pragma unroll
                for (int q = 0; q < 4; q++) {
                    int kk = q * 8 + khalf;
                    float4 v = __ldcg((const float4*)(g_RH + arow * HD + k0 + kk));
                    As[kk + 0][arow] = v.x;
                    As[kk + 1][arow] = v.y;
                    As[kk + 2][arow] = v.z;
                    As[kk + 3][arow] = v.w;
                }
                Bs[bkk][cbc] = Whc[(size_t)(k0 + bkk) * HD + ccol0 + cbc];
                __syncthreads();
                #pragma unroll
                for (int k = 0; k < 32; k++) {
                    float bv = Bs[k][ctx];
                    float4 a = *(const float4*)&As[k][cty * 4];
                    acc[0] += a.x * bv; acc[1] += a.y * bv;
                    acc[2] += a.z * bv; acc[3] += a.w * bv;
                }
                __syncthreads();
            }
            #pragma unroll
            for (int i = 0; i < 4; i++) {
                int row = cty * 4 + i;
                float cxv = cx[row * HD + cj];
                float chv = acc[i];
                float z = acj * cxv * chv + b1cj * cxv + b2cj * chv + bcj;
                float c = tanhf(z);
                float u = __ldcg(g_U + row * HD + cj);
                float hv = __ldcg(g_h + row * HD + cj);
                float hn = u * hv + (1.f - u) * c;
                __stcg(g_h + row * HD + cj, hn);
                outseq[(size_t)t * BD * HD + row * HD + cj] = hn;
            }
        }
        bar++; gsync(bar * nCTA);
    }
}

// ---------------- NCE sampled logits: [32768,1024] @ [1024,64] + softplus-reduce ---
__global__ __launch_bounds__(256)
void k_nce_samp(float* __restrict__ outsum)
{
    __shared__ float As[8][132];
    __shared__ float Bs[8][64];
    __shared__ float red[256];
    const int tid = threadIdx.x;
    const int rowBase = blockIdx.x * 128;

    const int arow = tid >> 1;
    const int acol = (tid & 1) << 2;
    int gi = rowBase + arow;                       // token index b*T + t
    size_t aoff = (size_t)((gi & 255) * BD + (gi >> 8)) * HD;  // row t*B+b in [T,B,H]

    const int brow = tid >> 5;                     // 0..7
    const int bcl  = (tid & 31) << 1;              // 0..62 (even)

    const int ty = tid >> 4;
    const int tx = tid & 15;

    float acc[8][4];
    #pragma unroll
    for (int i = 0; i < 8; i++)
        #pragma unroll
        for (int j = 0; j < 4; j++) acc[i][j] = 0.f;

    for (int k0 = 0; k0 < HD; k0 += 8) {
        float4 av = *(const float4*)(g_O1 + aoff + k0 + acol);
        As[acol + 0][arow] = av.x;
        As[acol + 1][arow] = av.y;
        As[acol + 2][arow] = av.z;
        As[acol + 3][arow] = av.w;
        float2 bw = *(const float2*)(g_sampWT + (size_t)(k0 + brow) * SD + bcl);
        Bs[brow][bcl]     = bw.x;
        Bs[brow][bcl + 1] = bw.y;
        __syncthreads();
        #pragma unroll
        for (int k = 0; k < 8; k++) {
            float ar[8], br[4];
            *(float4*)&ar[0] = *(const float4*)&As[k][ty * 8];
            *(float4*)&ar[4] = *(const float4*)&As[k][ty * 8 + 4];
            *(float4*)&br[0] = *(const float4*)&Bs[k][tx * 4];
            #pragma unroll
            for (int i = 0; i < 8; i++)
                #pragma unroll
                for (int j = 0; j < 4; j++)
                    acc[i][j] += ar[i] * br[j];
        }
        __syncthreads();
    }

    float s = 0.f;
    #pragma unroll
    for (int j = 0; j < 4; j++) {
        float sbv = g_sampB[tx * 4 + j];
        #pragma unroll
        for (int i = 0; i < 8; i++)
            s += softplusf(acc[i][j] + sbv);
    }
    red[tid] = s;
    __syncthreads();
    for (int o = 128; o > 0; o >>= 1) {
        if (tid < o) red[tid] += red[tid + o];
        __syncthreads();
    }
    if (tid == 0) atomicAdd(outsum, red[0] * (1.f / 32768.f));
}

// ---------------- NCE true logits: warp-per-token dot + softplus(-x) ----------------
__global__ __launch_bounds__(256)
void k_nce_true(const int* __restrict__ targets, const float* __restrict__ sw,
                const float* __restrict__ sb, float* __restrict__ outsum)
{
    __shared__ float red[8];
    const int warp = threadIdx.x >> 5;
    const int lane = threadIdx.x & 31;
    const int i = blockIdx.x * 8 + warp;           // token index b*T + t
    const int label = targets[i];
    const float* orow = g_O1 + (size_t)((i & 255) * BD + (i >> 8)) * HD;
    const float* wrow = sw + (size_t)label * HD;

    float s = 0.f;
    #pragma unroll
    for (int k0 = 0; k0 < HD; k0 += 128) {
        float4 a = *(const float4*)(orow + k0 + lane * 4);
        float4 w = *(const float4*)(wrow + k0 + lane * 4);
        s += a.x * w.x + a.y * w.y + a.z * w.z + a.w * w.w;
    }
    #pragma unroll
    for (int o = 16; o > 0; o >>= 1) s += __shfl_xor_sync(0xffffffffu, s, o);
    if (lane == 0) {
        float logit = s + sb[label];
        red[warp] = softplusf(-logit);
    }
    __syncthreads();
    if (threadIdx.x == 0) {
        float t = 0.f;
        #pragma unroll
        for (int w = 0; w < 8; w++) t += red[w];
        atomicAdd(outsum, t * (1.f / 32768.f));
    }
}

// ---------------- launch ----------------
extern "C" void kernel_launch(void* const* d_in, const int* in_sizes, int n_in,
                              void* d_out, int out_size)
{
    const int*   input_data = (const int*)  d_in[0];
    const int*   targets    = (const int*)  d_in[1];
    const int*   nce        = (const int*)  d_in[2];
    const float* embedding  = (const float*)d_in[3];
    const float* win        = (const float*)d_in[4];
    const float* bin_       = (const float*)d_in[5];
    const float* Wxg        = (const float*)d_in[6];
    const float* Whg        = (const float*)d_in[7];
    const float* ag         = (const float*)d_in[8];
    const float* b1g        = (const float*)d_in[9];
    const float* b2g        = (const float*)d_in[10];
    const float* bg         = (const float*)d_in[11];
    const float* Wxc        = (const float*)d_in[12];
    const float* Whc        = (const float*)d_in[13];
    const float* ac         = (const float*)d_in[14];
    const float* b1c        = (const float*)d_in[15];
    const float* b2c        = (const float*)d_in[16];
    const float* bc         = (const float*)d_in[17];
    const float* softmax_w  = (const float*)d_in[18];
    const float* softmax_b  = (const float*)d_in[19];
    float* out = (float*)d_out;

    float *pX, *pXG, *pXC, *pO0, *pO1;
    int* pidx;
    cudaGetSymbolAddress((void**)&pX,  g_X);
    cudaGetSymbolAddress((void**)&pXG, g_XG);
    cudaGetSymbolAddress((void**)&pXC, g_XC);
    cudaGetSymbolAddress((void**)&pO0, g_O0);
    cudaGetSymbolAddress((void**)&pO1, g_O1);
    cudaGetSymbolAddress((void**)&pidx, g_rowidx);

    k_zero_out<<<1, 32>>>(out, out_size);
    k_zero_bar<<<1, 1>>>();
    k_rowidx<<<TB / 256, 256>>>(input_data);

    // X = gather(embedding)[T,B] @ win + bin_
    k_sgemm<true, true><<<dim3(HD / 128, TB / 128), 256>>>(
        embedding, win, bin_, pX, TB, HD, ED, pidx);

    k_gather_samp<<<SD, 256>>>(nce, softmax_w, softmax_b);

    const float* inp = pX;
    float* outb[2] = {pO0, pO1};
    for (int l = 0; l < LD; l++) {
        // hoisted x-projections for the whole sequence (big batch GEMMs)
        k_sgemm<false, false><<<dim3(H2 / 128, TB / 128), 256>>>(
            inp, Wxg + (size_t)l * HD * H2, nullptr, pXG, TB, H2, HD, nullptr);
        k_sgemm<false, false><<<dim3(HD / 128, TB / 128), 256>>>(
            inp, Wxc + (size_t)l * HD * HD, nullptr, pXC, TB, HD, HD, nullptr);

        // persistent recurrence for this layer (128 CTAs, software grid barrier)
        unsigned barBase = (unsigned)l * (1u + 2u * TD);
        k_layer<<<128, 256>>>(
            Whg + (size_t)l * HD * H2, Whc + (size_t)l * HD * HD,
            pXG, pXC,
            ag  + (size_t)l * H2, b1g + (size_t)l * H2,
            b2g + (size_t)l * H2, bg  + (size_t)l * H2,
            ac  + (size_t)l * HD, b1c + (size_t)l * HD,
            b2c + (size_t)l * HD, bc  + (size_t)l * HD,
            outb[l], barBase);
        inp = outb[l];
    }

    k_nce_true<<<TB / 8, 256>>>(targets, softmax_w, softmax_b, out);
    k_nce_samp<<<TB / 128, 256>>>(out);
}

// round 6
// speedup vs baseline: 1.3392x; 1.3392x over previous
#include <cuda_runtime.h>
#include <cuda_bf16.h>
#include <stdint.h>
#include <math.h>

// Problem constants
#define VD 16384
#define ED 1024
#define HD 1024
#define H2 2048
#define LD 2
#define BD 128
#define TD 256
#define SD 64
#define TB 32768   // B*T

// ---------------- scratch (__device__ globals; no allocations allowed) -------------
__device__ float g_X [(size_t)TB * HD];   // projected inputs, [T,B,H] fp32
__device__ float g_XG[(size_t)TB * H2];   // per-layer x-gate proj fp32
__device__ float g_XC[(size_t)TB * HD];   // per-layer x-cand proj fp32
__device__ float g_O0[(size_t)TB * HD];
__device__ float g_O1[(size_t)TB * HD];
__device__ float g_h [BD * HD];
__device__ float g_RH[BD * HD];
__device__ float g_U [BD * HD];
__device__ float g_sampWT[HD * SD];
__device__ float g_sampB [SD];
__device__ int   g_rowidx[TB];
__device__ unsigned g_barcnt;

// bf16 operands for tensor-core GEMMs
__device__ __nv_bfloat16 g_Ab [(size_t)TB * HD];   // A operand (X or O0)
__device__ __nv_bfloat16 g_Eb [(size_t)VD * ED];   // embedding table bf16
__device__ __nv_bfloat16 g_WbT[(size_t)H2 * HD];   // transposed weight [N,K]

__device__ __forceinline__ float softplusf(float x) {
    return fmaxf(x, 0.f) + log1pf(expf(-fabsf(x)));
}

// ---------------- PTX helpers (sm_80-compatible: cp.async / ldmatrix / mma) --------
__device__ __forceinline__ uint32_t s2u(const void* p) {
    uint32_t a;
    asm("{ .reg .u64 t; cvta.to.shared.u64 t, %1; cvt.u32.u64 %0, t; }" : "=r"(a) : "l"(p));
    return a;
}
__device__ __forceinline__ void cp16(uint32_t dst, const void* src) {
    asm volatile("cp.async.cg.shared.global [%0], [%1], 16;" :: "r"(dst), "l"(src));
}
#define CP_COMMIT() asm volatile("cp.async.commit_group;" ::: "memory")
#define CP_WAIT(n)  asm volatile("cp.async.wait_group %0;" :: "n"(n) : "memory")

__device__ __forceinline__ void ldmatrix_x4(uint32_t& r0, uint32_t& r1,
                                            uint32_t& r2, uint32_t& r3, uint32_t addr) {
    asm volatile("ldmatrix.sync.aligned.m8n8.x4.shared.b16 {%0,%1,%2,%3}, [%4];"
                 : "=r"(r0), "=r"(r1), "=r"(r2), "=r"(r3) : "r"(addr));
}
__device__ __forceinline__ void mma16816(float* d, const uint32_t* a, const uint32_t* b) {
    asm volatile("mma.sync.aligned.m16n8k16.row.col.f32.bf16.bf16.f32 "
                 "{%0,%1,%2,%3},{%4,%5,%6,%7},{%8,%9},{%0,%1,%2,%3};"
                 : "+f"(d[0]), "+f"(d[1]), "+f"(d[2]), "+f"(d[3])
                 : "r"(a[0]), "r"(a[1]), "r"(a[2]), "r"(a[3]), "r"(b[0]), "r"(b[1]));
}

// software grid barrier
__device__ __forceinline__ void gsync(unsigned target) {
    __syncthreads();
    if (threadIdx.x == 0) {
        __threadfence();
        atomicAdd(&g_barcnt, 1u);
        while (*(volatile unsigned*)&g_barcnt < target) __nanosleep(32);
        __threadfence();
    }
    __syncthreads();
}

// ---------------- tiny helper kernels ----------------
__global__ void k_zero_out(float* p, int n) {
    int i = blockIdx.x * blockDim.x + threadIdx.x;
    if (i < n) p[i] = 0.f;
}
__global__ void k_zero_bar() { g_barcnt = 0u; }

__global__ void k_rowidx(const int* __restrict__ input_data) {
    int r = blockIdx.x * blockDim.x + threadIdx.x;
    if (r < TB) {
        int t = r >> 7, b = r & 127;
        g_rowidx[r] = input_data[b * TD + t];
    }
}

__global__ void k_gather_samp(const int* __restrict__ nce,
                              const float* __restrict__ sw,
                              const float* __restrict__ sb) {
    int s = blockIdx.x;
    int row = nce[s];
    const float* src = sw + (size_t)row * HD;
    for (int k = threadIdx.x; k < HD; k += blockDim.x)
        g_sampWT[k * SD + s] = src[k];
    if (threadIdx.x == 0) g_sampB[s] = sb[row];
}

// fp32 -> bf16 (vectorized by 4)
__global__ void k_f2b(const float* __restrict__ in, __nv_bfloat16* __restrict__ out, int n4) {
    int i = blockIdx.x * blockDim.x + threadIdx.x;
    if (i < n4) {
        float4 v = ((const float4*)in)[i];
        __nv_bfloat162* o = (__nv_bfloat162*)out;
        o[2 * i + 0] = __floats2bfloat162_rn(v.x, v.y);
        o[2 * i + 1] = __floats2bfloat162_rn(v.z, v.w);
    }
}

// fp32 [K,N] -> bf16 transposed [N,K]
__global__ void k_f2bT(const float* __restrict__ in, __nv_bfloat16* __restrict__ out,
                       int N, int K) {
    int i = blockIdx.x * blockDim.x + threadIdx.x;
    if (i < N * K) {
        int n = i / K, k = i - n * K;
        out[i] = __float2bfloat16(in[(size_t)k * N + n]);
    }
}

// ---------------- bf16 mma.sync GEMM: C[M,N] = A[M,1024] @ BT[N,1024]^T (+bias) -----
// 256 threads, 128x128 tile, K-step 32, 2-stage cp.async double buffer.
// 8 warps in 2(m) x 4(n) layout; warp tile 64x32 via m16n8k16.
#define LDP 40   // padded smem row stride in bf16 elements (80 bytes, conflict-free)

template<bool GATHER, bool BIAS>
__global__ __launch_bounds__(256)
void k_mgemm(const __nv_bfloat16* __restrict__ A, const __nv_bfloat16* __restrict__ BT,
             const float* __restrict__ bias, float* __restrict__ C,
             int N, const int* __restrict__ gidx)
{
    __shared__ __align__(16) __nv_bfloat16 sA[2][128 * LDP];
    __shared__ __align__(16) __nv_bfloat16 sB[2][128 * LDP];

    const int tid = threadIdx.x;
    const int rowBase = blockIdx.y * 128;
    const int colBase = blockIdx.x * 128;

    // ---- loader mapping: tid 0..127 -> A rows, 128..255 -> B rows ----
    const int lrow = tid & 127;
    const bool isB = tid >= 128;
    const __nv_bfloat16* src;
    if (isB) {
        src = BT + (size_t)(colBase + lrow) * 1024;
    } else {
        size_t ar = GATHER ? (size_t)gidx[rowBase + lrow] : (size_t)(rowBase + lrow);
        src = A + ar * 1024;
    }
    uint32_t dst0 = s2u(isB ? (const void*)&sB[0][lrow * LDP] : (const void*)&sA[0][lrow * LDP]);
    uint32_t dst1 = s2u(isB ? (const void*)&sB[1][lrow * LDP] : (const void*)&sA[1][lrow * LDP]);

    // ---- compute mapping ----
    const int wid = tid >> 5, lane = tid & 31;
    const int mb = (wid & 1) * 64;     // warp m base
    const int nb = (wid >> 1) * 32;    // warp n base
    const int arow_l = (lane & 7) + ((lane >> 3) & 1) * 8;  // A ldmatrix row-in-tile
    const int acol_l = (lane >> 4) * 8;                     // A ldmatrix k offset
    const int brow_l = (lane & 7) + (lane >> 4) * 8;        // B ldmatrix row-in-tile
    const int bcol_l = ((lane >> 3) & 1) * 8;               // B ldmatrix k offset
    const uint32_t aS0 = s2u(sA[0]), aS1 = s2u(sA[1]);
    const uint32_t bS0 = s2u(sB[0]), bS1 = s2u(sB[1]);

    float acc[4][4][4];
    #pragma unroll
    for (int mt = 0; mt < 4; mt++)
        #pragma unroll
        for (int nt = 0; nt < 4; nt++)
            #pragma unroll
            for (int q = 0; q < 4; q++) acc[mt][nt][q] = 0.f;

    const int S = 32;  // K=1024 / 32

    // prologue: stage 0
    {
        const __nv_bfloat16* p = src;
        #pragma unroll
        for (int c = 0; c < 4; c++) cp16(dst0 + c * 16, p + c * 8);
        CP_COMMIT();
    }

    for (int s = 0; s < S; s++) {
        if (s + 1 < S) {
            uint32_t d = ((s + 1) & 1) ? dst1 : dst0;
            const __nv_bfloat16* p = src + (s + 1) * 32;
            #pragma unroll
            for (int c = 0; c < 4; c++) cp16(d + c * 16, p + c * 8);
            CP_COMMIT();
            CP_WAIT(1);
        } else {
            CP_WAIT(0);
        }
        __syncthreads();

        const uint32_t aS = (s & 1) ? aS1 : aS0;
        const uint32_t bS = (s & 1) ? bS1 : bS0;
        #pragma unroll
        for (int kk = 0; kk < 32; kk += 16) {
            uint32_t af[4][4];
            #pragma unroll
            for (int mt = 0; mt < 4; mt++) {
                uint32_t ad = aS + (uint32_t)(((mb + mt * 16 + arow_l) * LDP) + kk + acol_l) * 2u;
                ldmatrix_x4(af[mt][0], af[mt][1], af[mt][2], af[mt][3], ad);
            }
            uint32_t bf[2][4];
            #pragma unroll
            for (int nt2 = 0; nt2 < 2; nt2++) {
                uint32_t bd = bS + (uint32_t)(((nb + nt2 * 16 + brow_l) * LDP) + kk + bcol_l) * 2u;
                ldmatrix_x4(bf[nt2][0], bf[nt2][1], bf[nt2][2], bf[nt2][3], bd);
            }
            #pragma unroll
            for (int mt = 0; mt < 4; mt++)
                #pragma unroll
                for (int nt = 0; nt < 4; nt++)
                    mma16816(acc[mt][nt], af[mt], &bf[nt >> 1][(nt & 1) * 2]);
        }
        __syncthreads();
    }

    // ---- epilogue: write fp32 C (+ optional bias) ----
    const int erow = lane >> 2;
    const int ecol = (lane & 3) * 2;
    #pragma unroll
    for (int mt = 0; mt < 4; mt++) {
        #pragma unroll
        for (int nt = 0; nt < 4; nt++) {
            int r0 = rowBase + mb + mt * 16 + erow;
            int c0 = colBase + nb + nt * 8 + ecol;
            float b0 = 0.f, b1 = 0.f;
            if (BIAS) { b0 = bias[c0]; b1 = bias[c0 + 1]; }
            float2 v0 = make_float2(acc[mt][nt][0] + b0, acc[mt][nt][1] + b1);
            float2 v1 = make_float2(acc[mt][nt][2] + b0, acc[mt][nt][3] + b1);
            *(float2*)&C[(size_t)r0 * N + c0] = v0;
            *(float2*)&C[(size_t)(r0 + 8) * N + c0] = v1;
        }
    }
}

// ---------------- persistent per-layer MI-GRU recurrence (fp32, weights in SMEM) ----
__global__ __launch_bounds__(256)
void k_layer2(const float* __restrict__ Whg, const float* __restrict__ Whc,
              const float* __restrict__ XG, const float* __restrict__ XC,
              const float* __restrict__ ag, const float* __restrict__ b1g,
              const float* __restrict__ b2g, const float* __restrict__ bg,
              const float* __restrict__ ac, const float* __restrict__ b1c,
              const float* __restrict__ b2c, const float* __restrict__ bcv,
              float* __restrict__ outseq, unsigned barBase)
{
    extern __shared__ float sm[];
    float* Wg = sm;                      // 1024 x 16
    float* Wc = sm + 16384;              // 1024 x 8
    float* As = sm + 16384 + 8192;       // 32 x 132

    const int cta = blockIdx.x;
    const unsigned nCTA = gridDim.x;
    const int tid = threadIdx.x;
    const int arow  = tid >> 1;
    const int khalf = (tid & 1) << 2;

    const int gcol0 = cta * 16;
    const int gtx = tid & 15;
    const int gty = tid >> 4;
    const int gj  = gcol0 + gtx;
    const float agj = ag[gj], b1gj = b1g[gj], b2gj = b2g[gj], bgj = bg[gj];

    const int ccol0 = cta * 8;
    const int ctx = tid & 7;
    const int cty = tid >> 3;
    const int cj  = ccol0 + ctx;
    const float acj = ac[cj], b1cj = b1c[cj], b2cj = b2c[cj], bcj = bcv[cj];

    // load this CTA's weight slices into SMEM once
    for (int i = tid; i < 1024 * 16; i += 256)
        Wg[i] = Whg[(size_t)(i >> 4) * H2 + gcol0 + (i & 15)];
    for (int i = tid; i < 1024 * 8; i += 256)
        Wc[i] = Whc[(size_t)(i >> 3) * HD + ccol0 + (i & 7)];

    { float4 z = make_float4(0.f, 0.f, 0.f, 0.f);
      __stcg((float4*)(g_h + cta * 1024 + tid * 4), z); }
    unsigned bar = barBase + 1;
    gsync(bar * nCTA);

    for (int t = 0; t < TD; t++) {
        // ---- gate phase ----
        {
            const float* gx = XG + (size_t)t * BD * H2;
            float gx8[8], h8[8];
            #pragma unroll
            for (int i = 0; i < 8; i++) {
                int row = gty * 8 + i;
                gx8[i] = gx[row * H2 + gj];
                h8[i]  = (gj < HD) ? __ldcg(g_h + row * HD + gj) : 0.f;
            }
            float acc[8] = {0.f,0.f,0.f,0.f,0.f,0.f,0.f,0.f};
            float4 pre[4];
            #pragma unroll
            for (int q = 0; q < 4; q++)
                pre[q] = __ldcg((const float4*)(g_h + arow * HD + q * 8 + khalf));
            for (int k0 = 0; k0 < HD; k0 += 32) {
                #pragma unroll
                for (int q = 0; q < 4; q++) {
                    int kk = q * 8 + khalf;
                    As[(kk + 0) * 132 + arow] = pre[q].x;
                    As[(kk + 1) * 132 + arow] = pre[q].y;
                    As[(kk + 2) * 132 + arow] = pre[q].z;
                    As[(kk + 3) * 132 + arow] = pre[q].w;
                }
                __syncthreads();
                if (k0 + 32 < HD) {
                    #pragma unroll
                    for (int q = 0; q < 4; q++)
                        pre[q] = __ldcg((const float4*)(g_h + arow * HD + (k0 + 32) + q * 8 + khalf));
                }
                const float* wrow = Wg + (size_t)k0 * 16;
                #pragma unroll
                for (int k = 0; k < 32; k++) {
                    float bv = wrow[k * 16 + gtx];
                    float4 a0 = *(const float4*)&As[k * 132 + gty * 8];
                    float4 a1 = *(const float4*)&As[k * 132 + gty * 8 + 4];
                    acc[0] += a0.x * bv; acc[1] += a0.y * bv;
                    acc[2] += a0.z * bv; acc[3] += a0.w * bv;
                    acc[4] += a1.x * bv; acc[5] += a1.y * bv;
                    acc[6] += a1.z * bv; acc[7] += a1.w * bv;
                }
                __syncthreads();
            }
            #pragma unroll
            for (int i = 0; i < 8; i++) {
                int row = gty * 8 + i;
                float z = agj * gx8[i] * acc[i] + b1gj * gx8[i] + b2gj * acc[i] + bgj;
                float g = 1.f / (1.f + expf(-z));
                if (gj < HD) __stcg(g_RH + row * HD + gj, g * h8[i]);
                else         __stcg(g_U + row * HD + (gj - HD), g);
            }
        }
        bar++; gsync(bar * nCTA);

        // ---- candidate phase ----
        {
            const float* cx = XC + (size_t)t * BD * HD;
            float cx4[4], u4[4], h4[4];
            #pragma unroll
            for (int i = 0; i < 4; i++) {
                int row = cty * 4 + i;
                cx4[i] = cx[row * HD + cj];
                u4[i]  = __ldcg(g_U + row * HD + cj);
                h4[i]  = __ldcg(g_h + row * HD + cj);
            }
            float acc[4] = {0.f, 0.f, 0.f, 0.f};
            float4 pre[4];
            #pragma unroll
            for (int q = 0; q < 4; q++)
                pre[q] = __ldcg((const float4*)(g_RH + arow * HD + q * 8 + khalf));
            for (int k0 = 0; k0 < HD; k0 += 32) {
                #pragma unroll
                for (int q = 0; q < 4; q++) {
                    int kk = q * 8 + khalf;
                    As[(kk + 0) * 132 + arow] = pre[q].x;
                    As[(kk + 1) * 132 + arow] = pre[q].y;
                    As[(kk + 2) * 132 + arow] = pre[q].z;
                    As[(kk + 3) * 132 + arow] = pre[q].w;
                }
                __syncthreads();
                if (k0 + 32 < HD) {
                    #pragma unroll
                    for (int q = 0; q < 4; q++)
                        pre[q] = __ldcg((const float4*)(g_RH + arow * HD + (k0 + 32) + q * 8 + khalf));
                }
                const float* wrow = Wc + (size_t)k0 * 8;
                #pragma unroll
                for (int k = 0; k < 32; k++) {
                    float bv = wrow[k * 8 + ctx];
                    float4 a = *(const float4*)&As[k * 132 + cty * 4];
                    acc[0] += a.x * bv; acc[1] += a.y * bv;
                    acc[2] += a.z * bv; acc[3] += a.w * bv;
                }
                __syncthreads();
            }
            #pragma unroll
            for (int i = 0; i < 4; i++) {
                int row = cty * 4 + i;
                float z = acj * cx4[i] * acc[i] + b1cj * cx4[i] + b2cj * acc[i] + bcj;
                float c = tanhf(z);
                float hn = u4[i] * h4[i] + (1.f - u4[i]) * c;
                __stcg(g_h + row * HD + cj, hn);
                outseq[(size_t)t * BD * HD + row * HD + cj] = hn;
            }
        }
        bar++; gsync(bar * nCTA);
    }
}

// ---------------- NCE sampled logits (fp32, small) ----------------
__global__ __launch_bounds__(256)
void k_nce_samp(float* __restrict__ outsum)
{
    __shared__ float As[8][132];
    __shared__ float Bs[8][64];
    __shared__ float red[256];
    const int tid = threadIdx.x;
    const int rowBase = blockIdx.x * 128;

    const int arow = tid >> 1;
    const int acol = (tid & 1) << 2;
    int gi = rowBase + arow;
    size_t aoff = (size_t)((gi & 255) * BD + (gi >> 8)) * HD;

    const int brow = tid >> 5;
    const int bcl  = (tid & 31) << 1;
    const int ty = tid >> 4;
    const int tx = tid & 15;

    float acc[8][4];
    #pragma unroll
    for (int i = 0; i < 8; i++)
        #pragma unroll
        for (int j = 0; j < 4; j++) acc[i][j] = 0.f;

    for (int k0 = 0; k0 < HD; k0 += 8) {
        float4 av = *(const float4*)(g_O1 + aoff + k0 + acol);
        As[acol + 0][arow] = av.x;
        As[acol + 1][arow] = av.y;
        As[acol + 2][arow] = av.z;
        As[acol + 3][arow] = av.w;
        float2 bw = *(const float2*)(g_sampWT + (size_t)(k0 + brow) * SD + bcl);
        Bs[brow][bcl]     = bw.x;
        Bs[brow][bcl + 1] = bw.y;
        __syncthreads();
        #pragma unroll
        for (int k = 0; k < 8; k++) {
            float ar[8], br[4];
            *(float4*)&ar[0] = *(const float4*)&As[k][ty * 8];
            *(float4*)&ar[4] = *(const float4*)&As[k][ty * 8 + 4];
            *(float4*)&br[0] = *(const float4*)&Bs[k][tx * 4];
            #pragma unroll
            for (int i = 0; i < 8; i++)
                #pragma unroll
                for (int j = 0; j < 4; j++)
                    acc[i][j] += ar[i] * br[j];
        }
        __syncthreads();
    }

    float s = 0.f;
    #pragma unroll
    for (int j = 0; j < 4; j++) {
        float sbv = g_sampB[tx * 4 + j];
        #pragma unroll
        for (int i = 0; i < 8; i++)
            s += softplusf(acc[i][j] + sbv);
    }
    red[tid] = s;
    __syncthreads();
    for (int o = 128; o > 0; o >>= 1) {
        if (tid < o) red[tid] += red[tid + o];
        __syncthreads();
    }
    if (tid == 0) atomicAdd(outsum, red[0] * (1.f / 32768.f));
}

__global__ __launch_bounds__(256)
void k_nce_true(const int* __restrict__ targets, const float* __restrict__ sw,
                const float* __restrict__ sb, float* __restrict__ outsum)
{
    __shared__ float red[8];
    const int warp = threadIdx.x >> 5;
    const int lane = threadIdx.x & 31;
    const int i = blockIdx.x * 8 + warp;
    const int label = targets[i];
    const float* orow = g_O1 + (size_t)((i & 255) * BD + (i >> 8)) * HD;
    const float* wrow = sw + (size_t)label * HD;

    float s = 0.f;
    #pragma unroll
    for (int k0 = 0; k0 < HD; k0 += 128) {
        float4 a = *(const float4*)(orow + k0 + lane * 4);
        float4 w = *(const float4*)(wrow + k0 + lane * 4);
        s += a.x * w.x + a.y * w.y + a.z * w.z + a.w * w.w;
    }
    #pragma unroll
    for (int o = 16; o > 0; o >>= 1) s += __shfl_xor_sync(0xffffffffu, s, o);
    if (lane == 0) {
        float logit = s + sb[label];
        red[warp] = softplusf(-logit);
    }
    __syncthreads();
    if (threadIdx.x == 0) {
        float t = 0.f;
        #pragma unroll
        for (int w = 0; w < 8; w++) t += red[w];
        atomicAdd(outsum, t * (1.f / 32768.f));
    }
}

// ---------------- launch ----------------
extern "C" void kernel_launch(void* const* d_in, const int* in_sizes, int n_in,
                              void* d_out, int out_size)
{
    const int*   input_data = (const int*)  d_in[0];
    const int*   targets    = (const int*)  d_in[1];
    const int*   nce        = (const int*)  d_in[2];
    const float* embedding  = (const float*)d_in[3];
    const float* win        = (const float*)d_in[4];
    const float* bin_       = (const float*)d_in[5];
    const float* Wxg        = (const float*)d_in[6];
    const float* Whg        = (const float*)d_in[7];
    const float* ag         = (const float*)d_in[8];
    const float* b1g        = (const float*)d_in[9];
    const float* b2g        = (const float*)d_in[10];
    const float* bg         = (const float*)d_in[11];
    const float* Wxc        = (const float*)d_in[12];
    const float* Whc        = (const float*)d_in[13];
    const float* ac         = (const float*)d_in[14];
    const float* b1c        = (const float*)d_in[15];
    const float* b2c        = (const float*)d_in[16];
    const float* bc         = (const float*)d_in[17];
    const float* softmax_w  = (const float*)d_in[18];
    const float* softmax_b  = (const float*)d_in[19];
    float* out = (float*)d_out;

    float *pX, *pXG, *pXC, *pO0, *pO1;
    int* pidx;
    __nv_bfloat16 *pAb, *pEb, *pWbT;
    cudaGetSymbolAddress((void**)&pX,  g_X);
    cudaGetSymbolAddress((void**)&pXG, g_XG);
    cudaGetSymbolAddress((void**)&pXC, g_XC);
    cudaGetSymbolAddress((void**)&pO0, g_O0);
    cudaGetSymbolAddress((void**)&pO1, g_O1);
    cudaGetSymbolAddress((void**)&pidx, g_rowidx);
    cudaGetSymbolAddress((void**)&pAb, g_Ab);
    cudaGetSymbolAddress((void**)&pEb, g_Eb);
    cudaGetSymbolAddress((void**)&pWbT, g_WbT);

    cudaFuncSetAttribute(k_layer2,
                         cudaFuncAttributeMaxDynamicSharedMemorySize, 115200);

    k_zero_out<<<1, 32>>>(out, out_size);
    k_zero_bar<<<1, 1>>>();
    k_rowidx<<<TB / 256, 256>>>(input_data);
    k_gather_samp<<<SD, 256>>>(nce, softmax_w, softmax_b);

    // embedding table -> bf16; win -> bf16 transposed
    k_f2b<<<(VD * ED / 4) / 256, 256>>>(embedding, pEb, VD * ED / 4);
    k_f2bT<<<(HD * ED) / 256, 256>>>(win, pWbT, HD, ED);

    // X = gather(Eb) @ win + bin_
    k_mgemm<true, true><<<dim3(HD / 128, TB / 128), 256>>>(
        pEb, pWbT, bin_, pX, HD, pidx);

    const float* inpF = pX;
    float* outb[2] = {pO0, pO1};
    for (int l = 0; l < LD; l++) {
        // A operand -> bf16
        k_f2b<<<((size_t)TB * HD / 4) / 256, 256>>>(inpF, pAb, TB * HD / 4);

        // XG = A @ Wxg[l]
        k_f2bT<<<(H2 * HD) / 256, 256>>>(Wxg + (size_t)l * HD * H2, pWbT, H2, HD);
        k_mgemm<false, false><<<dim3(H2 / 128, TB / 128), 256>>>(
            pAb, pWbT, nullptr, pXG, H2, nullptr);

        // XC = A @ Wxc[l]
        k_f2bT<<<(HD * HD) / 256, 256>>>(Wxc + (size_t)l * HD * HD, pWbT, HD, HD);
        k_mgemm<false, false><<<dim3(HD / 128, TB / 128), 256>>>(
            pAb, pWbT, nullptr, pXC, HD, nullptr);

        // persistent recurrence
        unsigned barBase = (unsigned)l * (1u + 2u * TD);
        k_layer2<<<128, 256, 115200>>>(
            Whg + (size_t)l * HD * H2, Whc + (size_t)l * HD * HD,
            pXG, pXC,
            ag  + (size_t)l * H2, b1g + (size_t)l * H2,
            b2g + (size_t)l * H2, bg  + (size_t)l * H2,
            ac  + (size_t)l * HD, b1c + (size_t)l * HD,
            b2c + (size_t)l * HD, bc  + (size_t)l * HD,
            outb[l], barBase);
        inpF = outb[l];
    }

    k_nce_true<<<TB / 8, 256>>>(targets, softmax_w, softmax_b, out);
    k_nce_samp<<<TB / 128, 256>>>(out);
}

// round 7
// speedup vs baseline: 3.2152x; 2.4008x over previous
#include <cuda_runtime.h>
#include <cuda_bf16.h>
#include <stdint.h>
#include <math.h>

// Problem constants
#define VD 16384
#define ED 1024
#define HD 1024
#define H2 2048
#define LD 2
#define BD 128
#define TD 256
#define SD 64
#define TB 32768   // B*T

// ---------------- scratch (__device__ globals; no allocations allowed) -------------
__device__ float g_X [(size_t)TB * HD];   // projected inputs, [T,B,H] fp32
__device__ float g_XG[(size_t)TB * H2];   // per-layer x-gate proj fp32
__device__ float g_XC[(size_t)TB * HD];   // per-layer x-cand proj fp32
__device__ float g_O0[(size_t)TB * HD];
__device__ float g_O1[(size_t)TB * HD];
__device__ float g_h [BD * HD];           // recurrent state fp32
__device__ __nv_bfloat16 g_hb [BD * HD];  // recurrent state bf16 (mma operand)
__device__ __nv_bfloat16 g_RHb[BD * HD];  // r*h bf16 (mma operand)
__device__ float g_U [BD * HD];           // update gate fp32
__device__ float g_sampWT[HD * SD];
__device__ float g_sampB [SD];
__device__ int   g_rowidx[TB];
__device__ unsigned g_barcnt;

// bf16 operands for tensor-core GEMMs
__device__ __nv_bfloat16 g_Ab [(size_t)TB * HD];   // A operand (X or O0)
__device__ __nv_bfloat16 g_Eb [(size_t)VD * ED];   // embedding table bf16
__device__ __nv_bfloat16 g_WbT[(size_t)H2 * HD];   // transposed weight [N,K]

__device__ __forceinline__ float softplusf(float x) {
    return fmaxf(x, 0.f) + log1pf(expf(-fabsf(x)));
}

// ---------------- PTX helpers (sm_80-compatible: cp.async / ldmatrix / mma) --------
__device__ __forceinline__ uint32_t s2u(const void* p) {
    uint32_t a;
    asm("{ .reg .u64 t; cvta.to.shared.u64 t, %1; cvt.u32.u64 %0, t; }" : "=r"(a) : "l"(p));
    return a;
}
__device__ __forceinline__ void cp16(uint32_t dst, const void* src) {
    asm volatile("cp.async.cg.shared.global [%0], [%1], 16;" :: "r"(dst), "l"(src));
}
#define CP_COMMIT() asm volatile("cp.async.commit_group;" ::: "memory")
#define CP_WAIT(n)  asm volatile("cp.async.wait_group %0;" :: "n"(n) : "memory")

__device__ __forceinline__ void ldmatrix_x4(uint32_t& r0, uint32_t& r1,
                                            uint32_t& r2, uint32_t& r3, uint32_t addr) {
    asm volatile("ldmatrix.sync.aligned.m8n8.x4.shared.b16 {%0,%1,%2,%3}, [%4];"
                 : "=r"(r0), "=r"(r1), "=r"(r2), "=r"(r3) : "r"(addr));
}
__device__ __forceinline__ void ldmatrix_x2(uint32_t& r0, uint32_t& r1, uint32_t addr) {
    asm volatile("ldmatrix.sync.aligned.m8n8.x2.shared.b16 {%0,%1}, [%2];"
                 : "=r"(r0), "=r"(r1) : "r"(addr));
}
__device__ __forceinline__ void mma16816(float* d, const uint32_t* a, const uint32_t* b) {
    asm volatile("mma.sync.aligned.m16n8k16.row.col.f32.bf16.bf16.f32 "
                 "{%0,%1,%2,%3},{%4,%5,%6,%7},{%8,%9},{%0,%1,%2,%3};"
                 : "+f"(d[0]), "+f"(d[1]), "+f"(d[2]), "+f"(d[3])
                 : "r"(a[0]), "r"(a[1]), "r"(a[2]), "r"(a[3]), "r"(b[0]), "r"(b[1]));
}

// software grid barrier
__device__ __forceinline__ void gsync(unsigned target) {
    __syncthreads();
    if (threadIdx.x == 0) {
        __threadfence();
        atomicAdd(&g_barcnt, 1u);
        while (*(volatile unsigned*)&g_barcnt < target) __nanosleep(32);
        __threadfence();
    }
    __syncthreads();
}

// ---------------- tiny helper kernels ----------------
__global__ void k_zero_out(float* p, int n) {
    int i = blockIdx.x * blockDim.x + threadIdx.x;
    if (i < n) p[i] = 0.f;
}
__global__ void k_zero_bar() { g_barcnt = 0u; }

__global__ void k_rowidx(const int* __restrict__ input_data) {
    int r = blockIdx.x * blockDim.x + threadIdx.x;
    if (r < TB) {
        int t = r >> 7, b = r & 127;
        g_rowidx[r] = input_data[b * TD + t];
    }
}

__global__ void k_gather_samp(const int* __restrict__ nce,
                              const float* __restrict__ sw,
                              const float* __restrict__ sb) {
    int s = blockIdx.x;
    int row = nce[s];
    const float* src = sw + (size_t)row * HD;
    for (int k = threadIdx.x; k < HD; k += blockDim.x)
        g_sampWT[k * SD + s] = src[k];
    if (threadIdx.x == 0) g_sampB[s] = sb[row];
}

// fp32 -> bf16 (vectorized by 4)
__global__ void k_f2b(const float* __restrict__ in, __nv_bfloat16* __restrict__ out, int n4) {
    int i = blockIdx.x * blockDim.x + threadIdx.x;
    if (i < n4) {
        float4 v = ((const float4*)in)[i];
        __nv_bfloat162* o = (__nv_bfloat162*)out;
        o[2 * i + 0] = __floats2bfloat162_rn(v.x, v.y);
        o[2 * i + 1] = __floats2bfloat162_rn(v.z, v.w);
    }
}

// fp32 [K,N] -> bf16 transposed [N,K]
__global__ void k_f2bT(const float* __restrict__ in, __nv_bfloat16* __restrict__ out,
                       int N, int K) {
    int i = blockIdx.x * blockDim.x + threadIdx.x;
    if (i < N * K) {
        int n = i / K, k = i - n * K;
        out[i] = __float2bfloat16(in[(size_t)k * N + n]);
    }
}

// ---------------- bf16 mma.sync GEMM: C[M,N] = A[M,1024] @ BT[N,1024]^T (+bias) -----
#define LDP 40   // padded smem row stride in bf16 elements

template<bool GATHER, bool BIAS>
__global__ __launch_bounds__(256)
void k_mgemm(const __nv_bfloat16* __restrict__ A, const __nv_bfloat16* __restrict__ BT,
             const float* __restrict__ bias, float* __restrict__ C,
             int N, const int* __restrict__ gidx)
{
    __shared__ __align__(16) __nv_bfloat16 sA[2][128 * LDP];
    __shared__ __align__(16) __nv_bfloat16 sB[2][128 * LDP];

    const int tid = threadIdx.x;
    const int rowBase = blockIdx.y * 128;
    const int colBase = blockIdx.x * 128;

    const int lrow = tid & 127;
    const bool isB = tid >= 128;
    const __nv_bfloat16* src;
    if (isB) {
        src = BT + (size_t)(colBase + lrow) * 1024;
    } else {
        size_t ar = GATHER ? (size_t)gidx[rowBase + lrow] : (size_t)(rowBase + lrow);
        src = A + ar * 1024;
    }
    uint32_t dst0 = s2u(isB ? (const void*)&sB[0][lrow * LDP] : (const void*)&sA[0][lrow * LDP]);
    uint32_t dst1 = s2u(isB ? (const void*)&sB[1][lrow * LDP] : (const void*)&sA[1][lrow * LDP]);

    const int wid = tid >> 5, lane = tid & 31;
    const int mb = (wid & 1) * 64;
    const int nb = (wid >> 1) * 32;
    const int arow_l = (lane & 7) + ((lane >> 3) & 1) * 8;
    const int acol_l = (lane >> 4) * 8;
    const int brow_l = (lane & 7) + (lane >> 4) * 8;
    const int bcol_l = ((lane >> 3) & 1) * 8;
    const uint32_t aS0 = s2u(sA[0]), aS1 = s2u(sA[1]);
    const uint32_t bS0 = s2u(sB[0]), bS1 = s2u(sB[1]);

    float acc[4][4][4];
    #pragma unroll
    for (int mt = 0; mt < 4; mt++)
        #pragma unroll
        for (int nt = 0; nt < 4; nt++)
            #pragma unroll
            for (int q = 0; q < 4; q++) acc[mt][nt][q] = 0.f;

    const int S = 32;
    {
        const __nv_bfloat16* p = src;
        #pragma unroll
        for (int c = 0; c < 4; c++) cp16(dst0 + c * 16, p + c * 8);
        CP_COMMIT();
    }

    for (int s = 0; s < S; s++) {
        if (s + 1 < S) {
            uint32_t d = ((s + 1) & 1) ? dst1 : dst0;
            const __nv_bfloat16* p = src + (s + 1) * 32;
            #pragma unroll
            for (int c = 0; c < 4; c++) cp16(d + c * 16, p + c * 8);
            CP_COMMIT();
            CP_WAIT(1);
        } else {
            CP_WAIT(0);
        }
        __syncthreads();

        const uint32_t aS = (s & 1) ? aS1 : aS0;
        const uint32_t bS = (s & 1) ? bS1 : bS0;
        #pragma unroll
        for (int kk = 0; kk < 32; kk += 16) {
            uint32_t af[4][4];
            #pragma unroll
            for (int mt = 0; mt < 4; mt++) {
                uint32_t ad = aS + (uint32_t)(((mb + mt * 16 + arow_l) * LDP) + kk + acol_l) * 2u;
                ldmatrix_x4(af[mt][0], af[mt][1], af[mt][2], af[mt][3], ad);
            }
            uint32_t bf[2][4];
            #pragma unroll
            for (int nt2 = 0; nt2 < 2; nt2++) {
                uint32_t bd = bS + (uint32_t)(((nb + nt2 * 16 + brow_l) * LDP) + kk + bcol_l) * 2u;
                ldmatrix_x4(bf[nt2][0], bf[nt2][1], bf[nt2][2], bf[nt2][3], bd);
            }
            #pragma unroll
            for (int mt = 0; mt < 4; mt++)
                #pragma unroll
                for (int nt = 0; nt < 4; nt++)
                    mma16816(acc[mt][nt], af[mt], &bf[nt >> 1][(nt & 1) * 2]);
        }
        __syncthreads();
    }

    const int erow = lane >> 2;
    const int ecol = (lane & 3) * 2;
    #pragma unroll
    for (int mt = 0; mt < 4; mt++) {
        #pragma unroll
        for (int nt = 0; nt < 4; nt++) {
            int r0 = rowBase + mb + mt * 16 + erow;
            int c0 = colBase + nb + nt * 8 + ecol;
            float b0 = 0.f, b1 = 0.f;
            if (BIAS) { b0 = bias[c0]; b1 = bias[c0 + 1]; }
            float2 v0 = make_float2(acc[mt][nt][0] + b0, acc[mt][nt][1] + b1);
            float2 v1 = make_float2(acc[mt][nt][2] + b0, acc[mt][nt][3] + b1);
            *(float2*)&C[(size_t)r0 * N + c0] = v0;
            *(float2*)&C[(size_t)(r0 + 8) * N + c0] = v1;
        }
    }
}

// ---------------- persistent per-layer MI-GRU recurrence (bf16 tensor-core) ---------
// 128 CTAs x 256 threads (8 warps). CTA owns gate cols [cta*16,+16) and cand cols
// [cta*8,+8). Matmuls: mma.sync bf16, A (h / r*h) staged via cp.async double buffer,
// weights resident in SMEM bf16. h state fp32 + bf16 shadow; all inter-CTA via .cg.
__global__ __launch_bounds__(256)
void k_layer3(const float* __restrict__ Whg, const float* __restrict__ Whc,
              const float* __restrict__ XG, const float* __restrict__ XC,
              const float* __restrict__ ag, const float* __restrict__ b1g,
              const float* __restrict__ b2g, const float* __restrict__ bg,
              const float* __restrict__ ac, const float* __restrict__ b1c,
              const float* __restrict__ b2c, const float* __restrict__ bcv,
              float* __restrict__ outseq, unsigned barBase)
{
    extern __shared__ char smRaw[];
    __nv_bfloat16* Wg  = (__nv_bfloat16*)smRaw;       // [16][1032] bf16
    __nv_bfloat16* Wc  = Wg + 16 * 1032;              // [8][1032]
    __nv_bfloat16* stg = Wc + 8 * 1032;               // 2 stages x 128x136

    const int cta = blockIdx.x;
    const unsigned nCTA = gridDim.x;
    const int tid = threadIdx.x;
    const int wid = tid >> 5, lane = tid & 31;
    const int gcol0 = cta * 16, ccol0 = cta * 8;
    const bool isR = (cta < 64);   // gate cols < 1024 -> reset gate, else update gate

    // weight slices -> SMEM bf16 ([n][k], stride 1032)
    for (int i = tid; i < 16 * 1024; i += 256) {
        int n = i & 15, k = i >> 4;
        Wg[n * 1032 + k] = __float2bfloat16(Whg[(size_t)k * H2 + gcol0 + n]);
    }
    for (int i = tid; i < 8 * 1024; i += 256) {
        int n = i & 7, k = i >> 3;
        Wc[n * 1032 + k] = __float2bfloat16(Whc[(size_t)k * HD + ccol0 + n]);
    }

    // ldmatrix lane mappings
    const int arow_l = (lane & 7) + ((lane >> 3) & 1) * 8;
    const int acol_l = (lane >> 4) * 8;
    const int brow_l = (lane & 7) + (lane >> 4) * 8;
    const int bcol_l = ((lane >> 3) & 1) * 8;
    const int l16 = lane & 15;

    const uint32_t stA0 = s2u(stg);
    const uint32_t stA1 = stA0 + 128u * 272u;
    const uint32_t wgB  = s2u(Wg);
    const uint32_t wcB  = s2u(Wc);

    // epilogue mapping (mma d-fragment)
    const int erow = lane >> 2;
    const int ecol = (lane & 3) * 2;
    const int r0 = wid * 16 + erow;

    // per-lane gate/cand constants
    float agv[2][2], b1v[2][2], b2v[2][2], bgv[2][2];
    #pragma unroll
    for (int nt = 0; nt < 2; nt++)
        #pragma unroll
        for (int j = 0; j < 2; j++) {
            int col = gcol0 + nt * 8 + ecol + j;
            agv[nt][j] = ag[col]; b1v[nt][j] = b1g[col];
            b2v[nt][j] = b2g[col]; bgv[nt][j] = bg[col];
        }
    float acv[2], b1cv[2], b2cv[2], bcvv[2];
    #pragma unroll
    for (int j = 0; j < 2; j++) {
        int col = ccol0 + ecol + j;
        acv[j] = ac[col]; b1cv[j] = b1c[col];
        b2cv[j] = b2c[col]; bcvv[j] = bcv[col];
    }

    // stage loader mapping: 256 threads, 2 threads/row, 8x16B each
    const int srow = tid & 127;
    const int scb  = (tid >> 7) * 8;                 // 16B-chunk base (0 or 8)
    const uint32_t sdst_off = (uint32_t)(srow * 272 + scb * 16);

    // init h = 0 (fp32 + bf16 shadow)
    {
        float4 z = make_float4(0.f, 0.f, 0.f, 0.f);
        __stcg((float4*)(g_h + cta * 1024 + tid * 4), z);
        uint2 zb = make_uint2(0u, 0u);
        __stcg((uint2*)(g_hb + cta * 1024 + tid * 4), zb);
    }
    unsigned bar = barBase + 1;
    gsync(bar * nCTA);

    for (int t = 0; t < TD; t++) {
        const float* XGt = XG + (size_t)t * BD * H2;
        const float* XCt = XC + (size_t)t * BD * HD;

        // ================= gate phase: gh = h @ Whg[:,slice16] =================
        {
            float acc[2][4];
            #pragma unroll
            for (int nt = 0; nt < 2; nt++)
                #pragma unroll
                for (int q = 0; q < 4; q++) acc[nt][q] = 0.f;

            // prologue chunk 0
            {
                const __nv_bfloat16* src = g_hb + (size_t)srow * 1024 + scb * 8;
                #pragma unroll
                for (int c = 0; c < 8; c++) cp16(stA0 + sdst_off + c * 16, src + c * 8);
                CP_COMMIT();
            }
            for (int chunk = 0; chunk < 8; chunk++) {
                if (chunk < 7) {
                    const __nv_bfloat16* src = g_hb + (size_t)srow * 1024 + (chunk + 1) * 128 + scb * 8;
                    uint32_t dst = (((chunk + 1) & 1) ? stA1 : stA0) + sdst_off;
                    #pragma unroll
                    for (int c = 0; c < 8; c++) cp16(dst + c * 16, src + c * 8);
                    CP_COMMIT();
                    CP_WAIT(1);
                } else {
                    CP_WAIT(0);
                }
                __syncthreads();
                uint32_t aB = (chunk & 1) ? stA1 : stA0;
                #pragma unroll
                for (int ks = 0; ks < 8; ks++) {
                    int kloc = ks * 16;
                    int kg = chunk * 128 + kloc;
                    uint32_t af[4];
                    ldmatrix_x4(af[0], af[1], af[2], af[3],
                        aB + (uint32_t)((wid * 16 + arow_l) * 272 + (kloc + acol_l) * 2));
                    uint32_t bf[4];
                    ldmatrix_x4(bf[0], bf[1], bf[2], bf[3],
                        wgB + (uint32_t)(brow_l * 2064 + (kg + bcol_l) * 2));
                    mma16816(acc[0], af, &bf[0]);
                    mma16816(acc[1], af, &bf[2]);
                }
                __syncthreads();
            }

            // epilogue: sigmoid gate; r-CTAs write RHb bf16, u-CTAs write U fp32
            #pragma unroll
            for (int nt = 0; nt < 2; nt++) {
                #pragma unroll
                for (int half = 0; half < 2; half++) {
                    int row = r0 + half * 8;
                    int col = gcol0 + nt * 8 + ecol;
                    float2 gxv = *(const float2*)(XGt + (size_t)row * H2 + col);
                    float gh0 = acc[nt][half * 2 + 0];
                    float gh1 = acc[nt][half * 2 + 1];
                    float z0 = agv[nt][0] * gxv.x * gh0 + b1v[nt][0] * gxv.x + b2v[nt][0] * gh0 + bgv[nt][0];
                    float z1 = agv[nt][1] * gxv.y * gh1 + b1v[nt][1] * gxv.y + b2v[nt][1] * gh1 + bgv[nt][1];
                    float s0 = 1.f / (1.f + expf(-z0));
                    float s1 = 1.f / (1.f + expf(-z1));
                    if (isR) {
                        float2 hv = __ldcg((const float2*)(g_h + (size_t)row * 1024 + col));
                        __nv_bfloat162 p = __floats2bfloat162_rn(s0 * hv.x, s1 * hv.y);
                        __stcg((uint32_t*)(g_RHb + (size_t)row * 1024 + col), *(uint32_t*)&p);
                    } else {
                        __stcg((float2*)(g_U + (size_t)row * 1024 + (col - 1024)),
                               make_float2(s0, s1));
                    }
                }
            }
        }
        bar++; gsync(bar * nCTA);

        // ================= cand phase: ch = (r*h) @ Whc[:,slice8] =================
        {
            float acc[4] = {0.f, 0.f, 0.f, 0.f};
            {
                const __nv_bfloat16* src = g_RHb + (size_t)srow * 1024 + scb * 8;
                #pragma unroll
                for (int c = 0; c < 8; c++) cp16(stA0 + sdst_off + c * 16, src + c * 8);
                CP_COMMIT();
            }
            for (int chunk = 0; chunk < 8; chunk++) {
                if (chunk < 7) {
                    const __nv_bfloat16* src = g_RHb + (size_t)srow * 1024 + (chunk + 1) * 128 + scb * 8;
                    uint32_t dst = (((chunk + 1) & 1) ? stA1 : stA0) + sdst_off;
                    #pragma unroll
                    for (int c = 0; c < 8; c++) cp16(dst + c * 16, src + c * 8);
                    CP_COMMIT();
                    CP_WAIT(1);
                } else {
                    CP_WAIT(0);
                }
                __syncthreads();
                uint32_t aB = (chunk & 1) ? stA1 : stA0;
                #pragma unroll
                for (int ks = 0; ks < 8; ks++) {
                    int kloc = ks * 16;
                    int kg = chunk * 128 + kloc;
                    uint32_t af[4];
                    ldmatrix_x4(af[0], af[1], af[2], af[3],
                        aB + (uint32_t)((wid * 16 + arow_l) * 272 + (kloc + acol_l) * 2));
                    uint32_t bf2[2];
                    ldmatrix_x2(bf2[0], bf2[1],
                        wcB + (uint32_t)((l16 & 7) * 2064 + (kg + (l16 >> 3) * 8) * 2));
                    mma16816(acc, af, bf2);
                }
                __syncthreads();
            }

            // epilogue: tanh candidate, state update, outputs
            #pragma unroll
            for (int half = 0; half < 2; half++) {
                int row = r0 + half * 8;
                int col = ccol0 + ecol;
                float2 cxv = *(const float2*)(XCt + (size_t)row * HD + col);
                float ch0 = acc[half * 2 + 0];
                float ch1 = acc[half * 2 + 1];
                float z0 = acv[0] * cxv.x * ch0 + b1cv[0] * cxv.x + b2cv[0] * ch0 + bcvv[0];
                float z1 = acv[1] * cxv.y * ch1 + b1cv[1] * cxv.y + b2cv[1] * ch1 + bcvv[1];
                float c0 = tanhf(z0), c1 = tanhf(z1);
                float2 uv = __ldcg((const float2*)(g_U + (size_t)row * 1024 + col));
                float2 hv = __ldcg((const float2*)(g_h + (size_t)row * 1024 + col));
                float hn0 = uv.x * hv.x + (1.f - uv.x) * c0;
                float hn1 = uv.y * hv.y + (1.f - uv.y) * c1;
                __stcg((float2*)(g_h + (size_t)row * 1024 + col), make_float2(hn0, hn1));
                __nv_bfloat162 p = __floats2bfloat162_rn(hn0, hn1);
                __stcg((uint32_t*)(g_hb + (size_t)row * 1024 + col), *(uint32_t*)&p);
                *(float2*)(outseq + (size_t)t * BD * HD + (size_t)row * HD + col) =
                    make_float2(hn0, hn1);
            }
        }
        bar++; gsync(bar * nCTA);
    }
}

// ---------------- NCE sampled logits (fp32, small) ----------------
__global__ __launch_bounds__(256)
void k_nce_samp(float* __restrict__ outsum)
{
    __shared__ float As[8][132];
    __shared__ float Bs[8][64];
    __shared__ float red[256];
    const int tid = threadIdx.x;
    const int rowBase = blockIdx.x * 128;

    const int arow = tid >> 1;
    const int acol = (tid & 1) << 2;
    int gi = rowBase + arow;
    size_t aoff = (size_t)((gi & 255) * BD + (gi >> 8)) * HD;

    const int brow = tid >> 5;
    const int bcl  = (tid & 31) << 1;
    const int ty = tid >> 4;
    const int tx = tid & 15;

    float acc[8][4];
    #pragma unroll
    for (int i = 0; i < 8; i++)
        #pragma unroll
        for (int j = 0; j < 4; j++) acc[i][j] = 0.f;

    for (int k0 = 0; k0 < HD; k0 += 8) {
        float4 av = *(const float4*)(g_O1 + aoff + k0 + acol);
        As[acol + 0][arow] = av.x;
        As[acol + 1][arow] = av.y;
        As[acol + 2][arow] = av.z;
        As[acol + 3][arow] = av.w;
        float2 bw = *(const float2*)(g_sampWT + (size_t)(k0 + brow) * SD + bcl);
        Bs[brow][bcl]     = bw.x;
        Bs[brow][bcl + 1] = bw.y;
        __syncthreads();
        #pragma unroll
        for (int k = 0; k < 8; k++) {
            float ar[8], br[4];
            *(float4*)&ar[0] = *(const float4*)&As[k][ty * 8];
            *(float4*)&ar[4] = *(const float4*)&As[k][ty * 8 + 4];
            *(float4*)&br[0] = *(const float4*)&Bs[k][tx * 4];
            #pragma unroll
            for (int i = 0; i < 8; i++)
                #pragma unroll
                for (int j = 0; j < 4; j++)
                    acc[i][j] += ar[i] * br[j];
        }
        __syncthreads();
    }

    float s = 0.f;
    #pragma unroll
    for (int j = 0; j < 4; j++) {
        float sbv = g_sampB[tx * 4 + j];
        #pragma unroll
        for (int i = 0; i < 8; i++)
            s += softplusf(acc[i][j] + sbv);
    }
    red[tid] = s;
    __syncthreads();
    for (int o = 128; o > 0; o >>= 1) {
        if (tid < o) red[tid] += red[tid + o];
        __syncthreads();
    }
    if (tid == 0) atomicAdd(outsum, red[0] * (1.f / 32768.f));
}

__global__ __launch_bounds__(256)
void k_nce_true(const int* __restrict__ targets, const float* __restrict__ sw,
                const float* __restrict__ sb, float* __restrict__ outsum)
{
    __shared__ float red[8];
    const int warp = threadIdx.x >> 5;
    const int lane = threadIdx.x & 31;
    const int i = blockIdx.x * 8 + warp;
    const int label = targets[i];
    const float* orow = g_O1 + (size_t)((i & 255) * BD + (i >> 8)) * HD;
    const float* wrow = sw + (size_t)label * HD;

    float s = 0.f;
    #pragma unroll
    for (int k0 = 0; k0 < HD; k0 += 128) {
        float4 a = *(const float4*)(orow + k0 + lane * 4);
        float4 w = *(const float4*)(wrow + k0 + lane * 4);
        s += a.x * w.x + a.y * w.y + a.z * w.z + a.w * w.w;
    }
    #pragma unroll
    for (int o = 16; o > 0; o >>= 1) s += __shfl_xor_sync(0xffffffffu, s, o);
    if (lane == 0) {
        float logit = s + sb[label];
        red[warp] = softplusf(-logit);
    }
    __syncthreads();
    if (threadIdx.x == 0) {
        float t = 0.f;
        #pragma unroll
        for (int w = 0; w < 8; w++) t += red[w];
        atomicAdd(outsum, t * (1.f / 32768.f));
    }
}

// ---------------- launch ----------------
extern "C" void kernel_launch(void* const* d_in, const int* in_sizes, int n_in,
                              void* d_out, int out_size)
{
    const int*   input_data = (const int*)  d_in[0];
    const int*   targets    = (const int*)  d_in[1];
    const int*   nce        = (const int*)  d_in[2];
    const float* embedding  = (const float*)d_in[3];
    const float* win        = (const float*)d_in[4];
    const float* bin_       = (const float*)d_in[5];
    const float* Wxg        = (const float*)d_in[6];
    const float* Whg        = (const float*)d_in[7];
    const float* ag         = (const float*)d_in[8];
    const float* b1g        = (const float*)d_in[9];
    const float* b2g        = (const float*)d_in[10];
    const float* bg         = (const float*)d_in[11];
    const float* Wxc        = (const float*)d_in[12];
    const float* Whc        = (const float*)d_in[13];
    const float* ac         = (const float*)d_in[14];
    const float* b1c        = (const float*)d_in[15];
    const float* b2c        = (const float*)d_in[16];
    const float* bc         = (const float*)d_in[17];
    const float* softmax_w  = (const float*)d_in[18];
    const float* softmax_b  = (const float*)d_in[19];
    float* out = (float*)d_out;

    float *pX, *pXG, *pXC, *pO0, *pO1;
    int* pidx;
    __nv_bfloat16 *pAb, *pEb, *pWbT;
    cudaGetSymbolAddress((void**)&pX,  g_X);
    cudaGetSymbolAddress((void**)&pXG, g_XG);
    cudaGetSymbolAddress((void**)&pXC, g_XC);
    cudaGetSymbolAddress((void**)&pO0, g_O0);
    cudaGetSymbolAddress((void**)&pO1, g_O1);
    cudaGetSymbolAddress((void**)&pidx, g_rowidx);
    cudaGetSymbolAddress((void**)&pAb, g_Ab);
    cudaGetSymbolAddress((void**)&pEb, g_Eb);
    cudaGetSymbolAddress((void**)&pWbT, g_WbT);

    // dynamic smem: Wg 33024 + Wc 16512 + stages 69632 = 119168 bytes
    cudaFuncSetAttribute(k_layer3,
                         cudaFuncAttributeMaxDynamicSharedMemorySize, 119168);

    k_zero_out<<<1, 32>>>(out, out_size);
    k_zero_bar<<<1, 1>>>();
    k_rowidx<<<TB / 256, 256>>>(input_data);
    k_gather_samp<<<SD, 256>>>(nce, softmax_w, softmax_b);

    // embedding table -> bf16; win -> bf16 transposed
    k_f2b<<<(VD * ED / 4) / 256, 256>>>(embedding, pEb, VD * ED / 4);
    k_f2bT<<<(HD * ED) / 256, 256>>>(win, pWbT, HD, ED);

    // X = gather(Eb) @ win + bin_
    k_mgemm<true, true><<<dim3(HD / 128, TB / 128), 256>>>(
        pEb, pWbT, bin_, pX, HD, pidx);

    const float* inpF = pX;
    float* outb[2] = {pO0, pO1};
    for (int l = 0; l < LD; l++) {
        // A operand -> bf16
        k_f2b<<<((size_t)TB * HD / 4) / 256, 256>>>(inpF, pAb, TB * HD / 4);

        // XG = A @ Wxg[l]
        k_f2bT<<<(H2 * HD) / 256, 256>>>(Wxg + (size_t)l * HD * H2, pWbT, H2, HD);
        k_mgemm<false, false><<<dim3(H2 / 128, TB / 128), 256>>>(
            pAb, pWbT, nullptr, pXG, H2, nullptr);

        // XC = A @ Wxc[l]
        k_f2bT<<<(HD * HD) / 256, 256>>>(Wxc + (size_t)l * HD * HD, pWbT, HD, HD);
        k_mgemm<false, false><<<dim3(HD / 128, TB / 128), 256>>>(
            pAb, pWbT, nullptr, pXC, HD, nullptr);

        // persistent tensor-core recurrence
        unsigned barBase = (unsigned)l * (1u + 2u * TD);
        k_layer3<<<128, 256, 119168>>>(
            Whg + (size_t)l * HD * H2, Whc + (size_t)l * HD * HD,
            pXG, pXC,
            ag  + (size_t)l * H2, b1g + (size_t)l * H2,
            b2g + (size_t)l * H2, bg  + (size_t)l * H2,
            ac  + (size_t)l * HD, b1c + (size_t)l * HD,
            b2c + (size_t)l * HD, bc  + (size_t)l * HD,
            outb[l], barBase);
        inpF = outb[l];
    }

    k_nce_true<<<TB / 8, 256>>>(targets, softmax_w, softmax_b, out);
    k_nce_samp<<<TB / 128, 256>>>(out);
}

// round 8
// speedup vs baseline: 3.4323x; 1.0675x over previous
#include <cuda_runtime.h>
#include <cuda_bf16.h>
#include <stdint.h>
#include <math.h>

// Problem constants
#define VD 16384
#define ED 1024
#define HD 1024
#define H2 2048
#define LD 2
#define BD 128
#define TD 256
#define SD 64
#define TB 32768   // B*T

// ---------------- scratch (__device__ globals; no allocations allowed) -------------
__device__ float g_X [(size_t)TB * HD];   // projected inputs, [T,B,H] fp32
__device__ float g_XG[(size_t)TB * H2];   // per-layer x-gate proj fp32
__device__ float g_XC[(size_t)TB * HD];   // per-layer x-cand proj fp32
__device__ float g_O0[(size_t)TB * HD];
__device__ float g_O1[(size_t)TB * HD];
__device__ float g_h [BD * HD];           // recurrent state fp32
__device__ __nv_bfloat16 g_hb [BD * HD];  // recurrent state bf16 (mma operand)
__device__ __nv_bfloat16 g_RHb[BD * HD];  // r*h bf16 (mma operand)
__device__ float g_U [BD * HD];           // update gate fp32
__device__ float g_sampWT[HD * SD];
__device__ float g_sampB [SD];
__device__ int   g_rowidx[TB];
__device__ unsigned g_barcnt;

// bf16 operands for tensor-core GEMMs
__device__ __nv_bfloat16 g_Ab [(size_t)TB * HD];   // A operand (X or O0)
__device__ __nv_bfloat16 g_Eb [(size_t)VD * ED];   // embedding table bf16
__device__ __nv_bfloat16 g_WbT[(size_t)H2 * HD];   // transposed weight [N,K]

__device__ __forceinline__ float softplusf(float x) {
    return fmaxf(x, 0.f) + log1pf(expf(-fabsf(x)));
}

// ---------------- PTX helpers (sm_80-compatible: cp.async / ldmatrix / mma) --------
__device__ __forceinline__ uint32_t s2u(const void* p) {
    uint32_t a;
    asm("{ .reg .u64 t; cvta.to.shared.u64 t, %1; cvt.u32.u64 %0, t; }" : "=r"(a) : "l"(p));
    return a;
}
__device__ __forceinline__ void cp16(uint32_t dst, const void* src) {
    asm volatile("cp.async.cg.shared.global [%0], [%1], 16;" :: "r"(dst), "l"(src));
}
#define CP_COMMIT() asm volatile("cp.async.commit_group;" ::: "memory")
#define CP_WAIT(n)  asm volatile("cp.async.wait_group %0;" :: "n"(n) : "memory")

__device__ __forceinline__ void ldmatrix_x4(uint32_t& r0, uint32_t& r1,
                                            uint32_t& r2, uint32_t& r3, uint32_t addr) {
    asm volatile("ldmatrix.sync.aligned.m8n8.x4.shared.b16 {%0,%1,%2,%3}, [%4];"
                 : "=r"(r0), "=r"(r1), "=r"(r2), "=r"(r3) : "r"(addr));
}
__device__ __forceinline__ void ldmatrix_x2(uint32_t& r0, uint32_t& r1, uint32_t addr) {
    asm volatile("ldmatrix.sync.aligned.m8n8.x2.shared.b16 {%0,%1}, [%2];"
                 : "=r"(r0), "=r"(r1) : "r"(addr));
}
__device__ __forceinline__ void mma16816(float* d, const uint32_t* a, const uint32_t* b) {
    asm volatile("mma.sync.aligned.m16n8k16.row.col.f32.bf16.bf16.f32 "
                 "{%0,%1,%2,%3},{%4,%5,%6,%7},{%8,%9},{%0,%1,%2,%3};"
                 : "+f"(d[0]), "+f"(d[1]), "+f"(d[2]), "+f"(d[3])
                 : "r"(a[0]), "r"(a[1]), "r"(a[2]), "r"(a[3]), "r"(b[0]), "r"(b[1]));
}

// software grid barrier
__device__ __forceinline__ void gsync(unsigned target) {
    __syncthreads();
    if (threadIdx.x == 0) {
        __threadfence();
        atomicAdd(&g_barcnt, 1u);
        while (*(volatile unsigned*)&g_barcnt < target) __nanosleep(16);
        __threadfence();
    }
    __syncthreads();
}

// ---------------- tiny helper kernels ----------------
__global__ void k_zero_out(float* p, int n) {
    int i = blockIdx.x * blockDim.x + threadIdx.x;
    if (i < n) p[i] = 0.f;
}
__global__ void k_zero_bar() { g_barcnt = 0u; }

__global__ void k_rowidx(const int* __restrict__ input_data) {
    int r = blockIdx.x * blockDim.x + threadIdx.x;
    if (r < TB) {
        int t = r >> 7, b = r & 127;
        g_rowidx[r] = input_data[b * TD + t];
    }
}

__global__ void k_gather_samp(const int* __restrict__ nce,
                              const float* __restrict__ sw,
                              const float* __restrict__ sb) {
    int s = blockIdx.x;
    int row = nce[s];
    const float* src = sw + (size_t)row * HD;
    for (int k = threadIdx.x; k < HD; k += blockDim.x)
        g_sampWT[k * SD + s] = src[k];
    if (threadIdx.x == 0) g_sampB[s] = sb[row];
}

// fp32 -> bf16 (vectorized by 4)
__global__ void k_f2b(const float* __restrict__ in, __nv_bfloat16* __restrict__ out, int n4) {
    int i = blockIdx.x * blockDim.x + threadIdx.x;
    if (i < n4) {
        float4 v = ((const float4*)in)[i];
        __nv_bfloat162* o = (__nv_bfloat162*)out;
        o[2 * i + 0] = __floats2bfloat162_rn(v.x, v.y);
        o[2 * i + 1] = __floats2bfloat162_rn(v.z, v.w);
    }
}

// fp32 [K,N] -> bf16 transposed [N,K], tiled through smem (coalesced both sides)
__global__ void k_f2bTt(const float* __restrict__ in, __nv_bfloat16* __restrict__ out,
                        int N, int K) {
    __shared__ float tile[32][33];
    const int n0 = blockIdx.x * 32;
    const int k0 = blockIdx.y * 32;
    const int tx = threadIdx.x, ty = threadIdx.y;   // 32 x 8
    #pragma unroll
    for (int j = 0; j < 4; j++)
        tile[ty + 8 * j][tx] = in[(size_t)(k0 + ty + 8 * j) * N + n0 + tx];
    __syncthreads();
    #pragma unroll
    for (int j = 0; j < 4; j++)
        out[(size_t)(n0 + ty + 8 * j) * K + k0 + tx] =
            __float2bfloat16(tile[tx][ty + 8 * j]);
}

// ---------------- bf16 mma.sync GEMM: C[M,N] = A[M,1024] @ BT[N,1024]^T (+bias) -----
#define LDP 40   // padded smem row stride in bf16 elements

template<bool GATHER, bool BIAS>
__global__ __launch_bounds__(256)
void k_mgemm(const __nv_bfloat16* __restrict__ A, const __nv_bfloat16* __restrict__ BT,
             const float* __restrict__ bias, float* __restrict__ C,
             int N, const int* __restrict__ gidx)
{
    __shared__ __align__(16) __nv_bfloat16 sA[2][128 * LDP];
    __shared__ __align__(16) __nv_bfloat16 sB[2][128 * LDP];

    const int tid = threadIdx.x;
    const int rowBase = blockIdx.y * 128;
    const int colBase = blockIdx.x * 128;

    const int lrow = tid & 127;
    const bool isB = tid >= 128;
    const __nv_bfloat16* src;
    if (isB) {
        src = BT + (size_t)(colBase + lrow) * 1024;
    } else {
        size_t ar = GATHER ? (size_t)gidx[rowBase + lrow] : (size_t)(rowBase + lrow);
        src = A + ar * 1024;
    }
    uint32_t dst0 = s2u(isB ? (const void*)&sB[0][lrow * LDP] : (const void*)&sA[0][lrow * LDP]);
    uint32_t dst1 = s2u(isB ? (const void*)&sB[1][lrow * LDP] : (const void*)&sA[1][lrow * LDP]);

    const int wid = tid >> 5, lane = tid & 31;
    const int mb = (wid & 1) * 64;
    const int nb = (wid >> 1) * 32;
    const int arow_l = (lane & 7) + ((lane >> 3) & 1) * 8;
    const int acol_l = (lane >> 4) * 8;
    const int brow_l = (lane & 7) + (lane >> 4) * 8;
    const int bcol_l = ((lane >> 3) & 1) * 8;
    const uint32_t aS0 = s2u(sA[0]), aS1 = s2u(sA[1]);
    const uint32_t bS0 = s2u(sB[0]), bS1 = s2u(sB[1]);

    float acc[4][4][4];
    #pragma unroll
    for (int mt = 0; mt < 4; mt++)
        #pragma unroll
        for (int nt = 0; nt < 4; nt++)
            #pragma unroll
            for (int q = 0; q < 4; q++) acc[mt][nt][q] = 0.f;

    const int S = 32;
    {
        const __nv_bfloat16* p = src;
        #pragma unroll
        for (int c = 0; c < 4; c++) cp16(dst0 + c * 16, p + c * 8);
        CP_COMMIT();
    }

    for (int s = 0; s < S; s++) {
        if (s + 1 < S) {
            uint32_t d = ((s + 1) & 1) ? dst1 : dst0;
            const __nv_bfloat16* p = src + (s + 1) * 32;
            #pragma unroll
            for (int c = 0; c < 4; c++) cp16(d + c * 16, p + c * 8);
            CP_COMMIT();
            CP_WAIT(1);
        } else {
            CP_WAIT(0);
        }
        __syncthreads();

        const uint32_t aS = (s & 1) ? aS1 : aS0;
        const uint32_t bS = (s & 1) ? bS1 : bS0;
        #pragma unroll
        for (int kk = 0; kk < 32; kk += 16) {
            uint32_t af[4][4];
            #pragma unroll
            for (int mt = 0; mt < 4; mt++) {
                uint32_t ad = aS + (uint32_t)(((mb + mt * 16 + arow_l) * LDP) + kk + acol_l) * 2u;
                ldmatrix_x4(af[mt][0], af[mt][1], af[mt][2], af[mt][3], ad);
            }
            uint32_t bf[2][4];
            #pragma unroll
            for (int nt2 = 0; nt2 < 2; nt2++) {
                uint32_t bd = bS + (uint32_t)(((nb + nt2 * 16 + brow_l) * LDP) + kk + bcol_l) * 2u;
                ldmatrix_x4(bf[nt2][0], bf[nt2][1], bf[nt2][2], bf[nt2][3], bd);
            }
            #pragma unroll
            for (int mt = 0; mt < 4; mt++)
                #pragma unroll
                for (int nt = 0; nt < 4; nt++)
                    mma16816(acc[mt][nt], af[mt], &bf[nt >> 1][(nt & 1) * 2]);
        }
        __syncthreads();
    }

    const int erow = lane >> 2;
    const int ecol = (lane & 3) * 2;
    #pragma unroll
    for (int mt = 0; mt < 4; mt++) {
        #pragma unroll
        for (int nt = 0; nt < 4; nt++) {
            int r0 = rowBase + mb + mt * 16 + erow;
            int c0 = colBase + nb + nt * 8 + ecol;
            float b0 = 0.f, b1 = 0.f;
            if (BIAS) { b0 = bias[c0]; b1 = bias[c0 + 1]; }
            float2 v0 = make_float2(acc[mt][nt][0] + b0, acc[mt][nt][1] + b1);
            float2 v1 = make_float2(acc[mt][nt][2] + b0, acc[mt][nt][3] + b1);
            *(float2*)&C[(size_t)r0 * N + c0] = v0;
            *(float2*)&C[(size_t)(r0 + 8) * N + c0] = v1;
        }
    }
}

// ---------------- persistent per-layer MI-GRU recurrence (bf16 tensor-core) ---------
// 128 CTAs x 256 threads. CTA owns gate cols [cta*16,+16) and cand cols [cta*8,+8).
// 4-stage cp.async pipeline for the h / r*h broadcast; epilogue operands prefetched
// before the mma loop; weights resident in SMEM bf16.
__global__ __launch_bounds__(256)
void k_layer3(const float* __restrict__ Whg, const float* __restrict__ Whc,
              const float* __restrict__ XG, const float* __restrict__ XC,
              const float* __restrict__ ag, const float* __restrict__ b1g,
              const float* __restrict__ b2g, const float* __restrict__ bg,
              const float* __restrict__ ac, const float* __restrict__ b1c,
              const float* __restrict__ b2c, const float* __restrict__ bcv,
              float* __restrict__ outseq, unsigned barBase)
{
    extern __shared__ char smRaw[];
    __nv_bfloat16* Wg  = (__nv_bfloat16*)smRaw;       // [16][1032] bf16 = 33024B
    __nv_bfloat16* Wc  = Wg + 16 * 1032;              // [8][1032]  = 16512B
    __nv_bfloat16* stg = Wc + 8 * 1032;               // 4 stages x 128x136 = 139264B

    const int cta = blockIdx.x;
    const unsigned nCTA = gridDim.x;
    const int tid = threadIdx.x;
    const int wid = tid >> 5, lane = tid & 31;
    const int gcol0 = cta * 16, ccol0 = cta * 8;
    const bool isR = (cta < 64);

    // weight slices -> SMEM bf16 ([n][k], stride 1032)
    for (int i = tid; i < 16 * 1024; i += 256) {
        int n = i & 15, k = i >> 4;
        Wg[n * 1032 + k] = __float2bfloat16(Whg[(size_t)k * H2 + gcol0 + n]);
    }
    for (int i = tid; i < 8 * 1024; i += 256) {
        int n = i & 7, k = i >> 3;
        Wc[n * 1032 + k] = __float2bfloat16(Whc[(size_t)k * HD + ccol0 + n]);
    }

    const int arow_l = (lane & 7) + ((lane >> 3) & 1) * 8;
    const int acol_l = (lane >> 4) * 8;
    const int brow_l = (lane & 7) + (lane >> 4) * 8;
    const int bcol_l = ((lane >> 3) & 1) * 8;
    const int l16 = lane & 15;

    const uint32_t stB = s2u(stg);                 // stage s at stB + s*34816
    const uint32_t wgB = s2u(Wg);
    const uint32_t wcB = s2u(Wc);

    const int erow = lane >> 2;
    const int ecol = (lane & 3) * 2;
    const int r0 = wid * 16 + erow;

    // per-lane gate/cand constants
    float agv[2][2], b1v[2][2], b2v[2][2], bgv[2][2];
    #pragma unroll
    for (int nt = 0; nt < 2; nt++)
        #pragma unroll
        for (int j = 0; j < 2; j++) {
            int col = gcol0 + nt * 8 + ecol + j;
            agv[nt][j] = ag[col]; b1v[nt][j] = b1g[col];
            b2v[nt][j] = b2g[col]; bgv[nt][j] = bg[col];
        }
    float acv[2], b1cv[2], b2cv[2], bcvv[2];
    #pragma unroll
    for (int j = 0; j < 2; j++) {
        int col = ccol0 + ecol + j;
        acv[j] = ac[col]; b1cv[j] = b1c[col];
        b2cv[j] = b2c[col]; bcvv[j] = bcv[col];
    }

    // stage loader mapping
    const int srow = tid & 127;
    const int scb  = (tid >> 7) * 8;
    const uint32_t sdst_off = (uint32_t)(srow * 272 + scb * 16);

    // init h
    {
        float4 z = make_float4(0.f, 0.f, 0.f, 0.f);
        __stcg((float4*)(g_h + cta * 1024 + tid * 4), z);
        uint2 zb = make_uint2(0u, 0u);
        __stcg((uint2*)(g_hb + cta * 1024 + tid * 4), zb);
    }
    unsigned bar = barBase + 1;
    gsync(bar * nCTA);

    for (int t = 0; t < TD; t++) {
        const float* XGt = XG + (size_t)t * BD * H2;
        const float* XCt = XC + (size_t)t * BD * HD;

        // ================= gate phase: gh = h @ Whg[:,slice16] =================
        {
            // prefetch epilogue operands (consumed after the mma pipeline)
            float2 gxv[2][2], hvp[2][2];
            #pragma unroll
            for (int nt = 0; nt < 2; nt++)
                #pragma unroll
                for (int half = 0; half < 2; half++) {
                    int row = r0 + half * 8;
                    int col = gcol0 + nt * 8 + ecol;
                    gxv[nt][half] = __ldcg((const float2*)(XGt + (size_t)row * H2 + col));
                    if (isR)
                        hvp[nt][half] = __ldcg((const float2*)(g_h + (size_t)row * 1024 + col));
                }

            float acc[2][4];
            #pragma unroll
            for (int nt = 0; nt < 2; nt++)
                #pragma unroll
                for (int q = 0; q < 4; q++) acc[nt][q] = 0.f;

            // prologue: issue chunks 0..2
            #pragma unroll
            for (int p = 0; p < 3; p++) {
                const __nv_bfloat16* src = g_hb + (size_t)srow * 1024 + p * 128 + scb * 8;
                uint32_t dst = stB + (uint32_t)p * 34816u + sdst_off;
                #pragma unroll
                for (int c = 0; c < 8; c++) cp16(dst + c * 16, src + c * 8);
                CP_COMMIT();
            }
            for (int chunk = 0; chunk < 8; chunk++) {
                if (chunk < 5) {
                    const __nv_bfloat16* src = g_hb + (size_t)srow * 1024 + (chunk + 3) * 128 + scb * 8;
                    uint32_t dst = stB + (uint32_t)((chunk + 3) & 3) * 34816u + sdst_off;
                    #pragma unroll
                    for (int c = 0; c < 8; c++) cp16(dst + c * 16, src + c * 8);
                    CP_COMMIT();
                    CP_WAIT(3);
                } else {
                    CP_WAIT(0);
                }
                __syncthreads();
                uint32_t aB = stB + (uint32_t)(chunk & 3) * 34816u;
                #pragma unroll
                for (int ks = 0; ks < 8; ks++) {
                    int kloc = ks * 16;
                    int kg = chunk * 128 + kloc;
                    uint32_t af[4];
                    ldmatrix_x4(af[0], af[1], af[2], af[3],
                        aB + (uint32_t)((wid * 16 + arow_l) * 272 + (kloc + acol_l) * 2));
                    uint32_t bf[4];
                    ldmatrix_x4(bf[0], bf[1], bf[2], bf[3],
                        wgB + (uint32_t)(brow_l * 2064 + (kg + bcol_l) * 2));
                    mma16816(acc[0], af, &bf[0]);
                    mma16816(acc[1], af, &bf[2]);
                }
                __syncthreads();
            }

            // epilogue: sigmoid gate; r-CTAs write RHb bf16, u-CTAs write U fp32
            #pragma unroll
            for (int nt = 0; nt < 2; nt++) {
                #pragma unroll
                for (int half = 0; half < 2; half++) {
                    int row = r0 + half * 8;
                    int col = gcol0 + nt * 8 + ecol;
                    float gh0 = acc[nt][half * 2 + 0];
                    float gh1 = acc[nt][half * 2 + 1];
                    float gx0 = gxv[nt][half].x, gx1 = gxv[nt][half].y;
                    float z0 = agv[nt][0] * gx0 * gh0 + b1v[nt][0] * gx0 + b2v[nt][0] * gh0 + bgv[nt][0];
                    float z1 = agv[nt][1] * gx1 * gh1 + b1v[nt][1] * gx1 + b2v[nt][1] * gh1 + bgv[nt][1];
                    float s0 = 1.f / (1.f + expf(-z0));
                    float s1 = 1.f / (1.f + expf(-z1));
                    if (isR) {
                        __nv_bfloat162 p = __floats2bfloat162_rn(s0 * hvp[nt][half].x,
                                                                 s1 * hvp[nt][half].y);
                        __stcg((uint32_t*)(g_RHb + (size_t)row * 1024 + col), *(uint32_t*)&p);
                    } else {
                        __stcg((float2*)(g_U + (size_t)row * 1024 + (col - 1024)),
                               make_float2(s0, s1));
                    }
                }
            }
        }
        bar++; gsync(bar * nCTA);

        // ================= cand phase: ch = (r*h) @ Whc[:,slice8] =================
        {
            // prefetch epilogue operands
            float2 cxv[2], uvp[2], hvp2[2];
            #pragma unroll
            for (int half = 0; half < 2; half++) {
                int row = r0 + half * 8;
                int col = ccol0 + ecol;
                cxv[half]  = __ldcg((const float2*)(XCt + (size_t)row * HD + col));
                uvp[half]  = __ldcg((const float2*)(g_U + (size_t)row * 1024 + col));
                hvp2[half] = __ldcg((const float2*)(g_h + (size_t)row * 1024 + col));
            }

            float acc[4] = {0.f, 0.f, 0.f, 0.f};
            #pragma unroll
            for (int p = 0; p < 3; p++) {
                const __nv_bfloat16* src = g_RHb + (size_t)srow * 1024 + p * 128 + scb * 8;
                uint32_t dst = stB + (uint32_t)p * 34816u + sdst_off;
                #pragma unroll
                for (int c = 0; c < 8; c++) cp16(dst + c * 16, src + c * 8);
                CP_COMMIT();
            }
            for (int chunk = 0; chunk < 8; chunk++) {
                if (chunk < 5) {
                    const __nv_bfloat16* src = g_RHb + (size_t)srow * 1024 + (chunk + 3) * 128 + scb * 8;
                    uint32_t dst = stB + (uint32_t)((chunk + 3) & 3) * 34816u + sdst_off;
                    #pragma unroll
                    for (int c = 0; c < 8; c++) cp16(dst + c * 16, src + c * 8);
                    CP_COMMIT();
                    CP_WAIT(3);
                } else {
                    CP_WAIT(0);
                }
                __syncthreads();
                uint32_t aB = stB + (uint32_t)(chunk & 3) * 34816u;
                #pragma unroll
                for (int ks = 0; ks < 8; ks++) {
                    int kloc = ks * 16;
                    int kg = chunk * 128 + kloc;
                    uint32_t af[4];
                    ldmatrix_x4(af[0], af[1], af[2], af[3],
                        aB + (uint32_t)((wid * 16 + arow_l) * 272 + (kloc + acol_l) * 2));
                    uint32_t bf2[2];
                    ldmatrix_x2(bf2[0], bf2[1],
                        wcB + (uint32_t)((l16 & 7) * 2064 + (kg + (l16 >> 3) * 8) * 2));
                    mma16816(acc, af, bf2);
                }
                __syncthreads();
            }

            // epilogue: tanh candidate, state update, outputs
            #pragma unroll
            for (int half = 0; half < 2; half++) {
                int row = r0 + half * 8;
                int col = ccol0 + ecol;
                float ch0 = acc[half * 2 + 0];
                float ch1 = acc[half * 2 + 1];
                float cx0 = cxv[half].x, cx1 = cxv[half].y;
                float z0 = acv[0] * cx0 * ch0 + b1cv[0] * cx0 + b2cv[0] * ch0 + bcvv[0];
                float z1 = acv[1] * cx1 * ch1 + b1cv[1] * cx1 + b2cv[1] * ch1 + bcvv[1];
                float c0 = tanhf(z0), c1 = tanhf(z1);
                float hn0 = uvp[half].x * hvp2[half].x + (1.f - uvp[half].x) * c0;
                float hn1 = uvp[half].y * hvp2[half].y + (1.f - uvp[half].y) * c1;
                __stcg((float2*)(g_h + (size_t)row * 1024 + col), make_float2(hn0, hn1));
                __nv_bfloat162 p = __floats2bfloat162_rn(hn0, hn1);
                __stcg((uint32_t*)(g_hb + (size_t)row * 1024 + col), *(uint32_t*)&p);
                *(float2*)(outseq + (size_t)t * BD * HD + (size_t)row * HD + col) =
                    make_float2(hn0, hn1);
            }
        }
        bar++; gsync(bar * nCTA);
    }
}

// ---------------- NCE sampled logits (fp32, small) ----------------
__global__ __launch_bounds__(256)
void k_nce_samp(float* __restrict__ outsum)
{
    __shared__ float As[8][132];
    __shared__ float Bs[8][64];
    __shared__ float red[256];
    const int tid = threadIdx.x;
    const int rowBase = blockIdx.x * 128;

    const int arow = tid >> 1;
    const int acol = (tid & 1) << 2;
    int gi = rowBase + arow;
    size_t aoff = (size_t)((gi & 255) * BD + (gi >> 8)) * HD;

    const int brow = tid >> 5;
    const int bcl  = (tid & 31) << 1;
    const int ty = tid >> 4;
    const int tx = tid & 15;

    float acc[8][4];
    #pragma unroll
    for (int i = 0; i < 8; i++)
        #pragma unroll
        for (int j = 0; j < 4; j++) acc[i][j] = 0.f;

    for (int k0 = 0; k0 < HD; k0 += 8) {
        float4 av = *(const float4*)(g_O1 + aoff + k0 + acol);
        As[acol + 0][arow] = av.x;
        As[acol + 1][arow] = av.y;
        As[acol + 2][arow] = av.z;
        As[acol + 3][arow] = av.w;
        float2 bw = *(const float2*)(g_sampWT + (size_t)(k0 + brow) * SD + bcl);
        Bs[brow][bcl]     = bw.x;
        Bs[brow][bcl + 1] = bw.y;
        __syncthreads();
        #pragma unroll
        for (int k = 0; k < 8; k++) {
            float ar[8], br[4];
            *(float4*)&ar[0] = *(const float4*)&As[k][ty * 8];
            *(float4*)&ar[4] = *(const float4*)&As[k][ty * 8 + 4];
            *(float4*)&br[0] = *(const float4*)&Bs[k][tx * 4];
            #pragma unroll
            for (int i = 0; i < 8; i++)
                #pragma unroll
                for (int j = 0; j < 4; j++)
                    acc[i][j] += ar[i] * br[j];
        }
        __syncthreads();
    }

    float s = 0.f;
    #pragma unroll
    for (int j = 0; j < 4; j++) {
        float sbv = g_sampB[tx * 4 + j];
        #pragma unroll
        for (int i = 0; i < 8; i++)
            s += softplusf(acc[i][j] + sbv);
    }
    red[tid] = s;
    __syncthreads();
    for (int o = 128; o > 0; o >>= 1) {
        if (tid < o) red[tid] += red[tid + o];
        __syncthreads();
    }
    if (tid == 0) atomicAdd(outsum, red[0] * (1.f / 32768.f));
}

__global__ __launch_bounds__(256)
void k_nce_true(const int* __restrict__ targets, const float* __restrict__ sw,
                const float* __restrict__ sb, float* __restrict__ outsum)
{
    __shared__ float red[8];
    const int warp = threadIdx.x >> 5;
    const int lane = threadIdx.x & 31;
    const int i = blockIdx.x * 8 + warp;
    const int label = targets[i];
    const float* orow = g_O1 + (size_t)((i & 255) * BD + (i >> 8)) * HD;
    const float* wrow = sw + (size_t)label * HD;

    float s = 0.f;
    #pragma unroll
    for (int k0 = 0; k0 < HD; k0 += 128) {
        float4 a = *(const float4*)(orow + k0 + lane * 4);
        float4 w = *(const float4*)(wrow + k0 + lane * 4);
        s += a.x * w.x + a.y * w.y + a.z * w.z + a.w * w.w;
    }
    #pragma unroll
    for (int o = 16; o > 0; o >>= 1) s += __shfl_xor_sync(0xffffffffu, s, o);
    if (lane == 0) {
        float logit = s + sb[label];
        red[warp] = softplusf(-logit);
    }
    __syncthreads();
    if (threadIdx.x == 0) {
        float t = 0.f;
        #pragma unroll
        for (int w = 0; w < 8; w++) t += red[w];
        atomicAdd(outsum, t * (1.f / 32768.f));
    }
}

// ---------------- launch ----------------
extern "C" void kernel_launch(void* const* d_in, const int* in_sizes, int n_in,
                              void* d_out, int out_size)
{
    const int*   input_data = (const int*)  d_in[0];
    const int*   targets    = (const int*)  d_in[1];
    const int*   nce        = (const int*)  d_in[2];
    const float* embedding  = (const float*)d_in[3];
    const float* win        = (const float*)d_in[4];
    const float* bin_       = (const float*)d_in[5];
    const float* Wxg        = (const float*)d_in[6];
    const float* Whg        = (const float*)d_in[7];
    const float* ag         = (const float*)d_in[8];
    const float* b1g        = (const float*)d_in[9];
    const float* b2g        = (const float*)d_in[10];
    const float* bg         = (const float*)d_in[11];
    const float* Wxc        = (const float*)d_in[12];
    const float* Whc        = (const float*)d_in[13];
    const float* ac         = (const float*)d_in[14];
    const float* b1c        = (const float*)d_in[15];
    const float* b2c        = (const float*)d_in[16];
    const float* bc         = (const float*)d_in[17];
    const float* softmax_w  = (const float*)d_in[18];
    const float* softmax_b  = (const float*)d_in[19];
    float* out = (float*)d_out;

    float *pX, *pXG, *pXC, *pO0, *pO1;
    int* pidx;
    __nv_bfloat16 *pAb, *pEb, *pWbT;
    cudaGetSymbolAddress((void**)&pX,  g_X);
    cudaGetSymbolAddress((void**)&pXG, g_XG);
    cudaGetSymbolAddress((void**)&pXC, g_XC);
    cudaGetSymbolAddress((void**)&pO0, g_O0);
    cudaGetSymbolAddress((void**)&pO1, g_O1);
    cudaGetSymbolAddress((void**)&pidx, g_rowidx);
    cudaGetSymbolAddress((void**)&pAb, g_Ab);
    cudaGetSymbolAddress((void**)&pEb, g_Eb);
    cudaGetSymbolAddress((void**)&pWbT, g_WbT);

    // dynamic smem: Wg 33024 + Wc 16512 + 4 stages x 34816 = 188800 bytes
    cudaFuncSetAttribute(k_layer3,
                         cudaFuncAttributeMaxDynamicSharedMemorySize, 188800);

    k_zero_out<<<1, 32>>>(out, out_size);
    k_zero_bar<<<1, 1>>>();
    k_rowidx<<<TB / 256, 256>>>(input_data);
    k_gather_samp<<<SD, 256>>>(nce, softmax_w, softmax_b);

    // embedding table -> bf16; win -> bf16 transposed
    k_f2b<<<(VD * ED / 4) / 256, 256>>>(embedding, pEb, VD * ED / 4);
    k_f2bTt<<<dim3(HD / 32, ED / 32), dim3(32, 8)>>>(win, pWbT, HD, ED);

    // X = gather(Eb) @ win + bin_
    k_mgemm<true, true><<<dim3(HD / 128, TB / 128), 256>>>(
        pEb, pWbT, bin_, pX, HD, pidx);

    const float* inpF = pX;
    float* outb[2] = {pO0, pO1};
    for (int l = 0; l < LD; l++) {
        // A operand -> bf16
        k_f2b<<<((size_t)TB * HD / 4) / 256, 256>>>(inpF, pAb, TB * HD / 4);

        // XG = A @ Wxg[l]
        k_f2bTt<<<dim3(H2 / 32, HD / 32), dim3(32, 8)>>>(
            Wxg + (size_t)l * HD * H2, pWbT, H2, HD);
        k_mgemm<false, false><<<dim3(H2 / 128, TB / 128), 256>>>(
            pAb, pWbT, nullptr, pXG, H2, nullptr);

        // XC = A @ Wxc[l]
        k_f2bTt<<<dim3(HD / 32, HD / 32), dim3(32, 8)>>>(
            Wxc + (size_t)l * HD * HD, pWbT, HD, HD);
        k_mgemm<false, false><<<dim3(HD / 128, TB / 128), 256>>>(
            pAb, pWbT, nullptr, pXC, HD, nullptr);

        // persistent tensor-core recurrence
        unsigned barBase = (unsigned)l * (1u + 2u * TD);
        k_layer3<<<128, 256, 188800>>>(
            Whg + (size_t)l * HD * H2, Whc + (size_t)l * HD * HD,
            pXG, pXC,
            ag  + (size_t)l * H2, b1g + (size_t)l * H2,
            b2g + (size_t)l * H2, bg  + (size_t)l * H2,
            ac  + (size_t)l * HD, b1c + (size_t)l * HD,
            b2c + (size_t)l * HD, bc  + (size_t)l * HD,
            outb[l], barBase);
        inpF = outb[l];
    }

    k_nce_true<<<TB / 8, 256>>>(targets, softmax_w, softmax_b, out);
    k_nce_samp<<<TB / 128, 256>>>(out);
}